// round 14
// baseline (speedup 1.0000x reference)
#include <cuda_runtime.h>
#include <cuda_bf16.h>
#include <cuda_fp16.h>
#include <math.h>
#include <stdint.h>

#define NODES_MAX 100000
#define EDGES_MAX 1600000
#define GRAPHS_MAX 2048

// ---------------- scratch (no allocations allowed) ----------------
__device__ __half g_xwh [NODES_MAX * 128];   // conv1: fp16(x @ W1)
__device__ __half g_xwh2[NODES_MAX * 128];   // conv2: fp16(h @ W2)
__device__ float  g_dinv[NODES_MAX];         // rsqrt(deg+1)
__device__ float  g_sums[GRAPHS_MAX * 128];  // pooled sums (self-cleaned by gru)
__device__ float  g_cnt [GRAPHS_MAX];        // nodes per graph (self-cleaned by gru)
__device__ uint4  g_wbuf1[4096];             // W1 bf16 fragment order {bh0,bh1,bl0,bl1}
__device__ uint4  g_wbuf2[4096];             // W2 likewise
// CSR build
__device__ int    g_deg   [NODES_MAX];       // self-cleaned by scan3
__device__ int    g_scan  [NODES_MAX];
__device__ int    g_bsum  [1024];
__device__ int    g_boff  [1024];
__device__ int    g_rowptr[NODES_MAX + 1];
__device__ int    g_cursor[NODES_MAX];
__device__ int2   g_epack [EDGES_MAX];       // {src, bits(dinv[src]*dinv[dst])} sorted by dst

// ---------------- helpers ----------------
__device__ __forceinline__ void red_add_v4(float* addr, float4 v) {
    asm volatile("red.global.add.v4.f32 [%0], {%1,%2,%3,%4};"
                 :: "l"(addr), "f"(v.x), "f"(v.y), "f"(v.z), "f"(v.w) : "memory");
}
__device__ __forceinline__ void mma_bf16(float* c, const uint32_t* a, const uint32_t* b) {
    asm volatile(
        "mma.sync.aligned.m16n8k16.row.col.f32.bf16.bf16.f32 "
        "{%0,%1,%2,%3},{%4,%5,%6,%7},{%8,%9},{%0,%1,%2,%3};"
        : "+f"(c[0]), "+f"(c[1]), "+f"(c[2]), "+f"(c[3])
        : "r"(a[0]), "r"(a[1]), "r"(a[2]), "r"(a[3]), "r"(b[0]), "r"(b[1]));
}
__device__ __forceinline__ uint32_t smem_u32(const void* p) {
    uint32_t a;
    asm("{ .reg .u64 t; cvta.to.shared.u64 t, %1; cvt.u32.u64 %0, t; }" : "=r"(a) : "l"(p));
    return a;
}
__device__ __forceinline__ void cp_async16(uint32_t dst, const void* src, bool pred) {
    int sz = pred ? 16 : 0;
    asm volatile("cp.async.cg.shared.global [%0], [%1], 16, %2;"
                 :: "r"(dst), "l"(src), "r"(sz) : "memory");
}
__device__ __forceinline__ void cp_commit() {
    asm volatile("cp.async.commit_group;" ::: "memory");
}
template <int NW>
__device__ __forceinline__ void cp_wait_group() {
    asm volatile("cp.async.wait_group %0;" :: "n"(NW) : "memory");
}
__device__ __forceinline__ uint32_t bf16pack_r(float v0, float v1, float& r0, float& r1) {
    __nv_bfloat16 h0 = __float2bfloat16(v0);
    __nv_bfloat16 h1 = __float2bfloat16(v1);
    r0 = v0 - __bfloat162float(h0);
    r1 = v1 - __bfloat162float(h1);
    return ((uint32_t)__bfloat16_as_ushort(h1) << 16) | (uint32_t)__bfloat16_as_ushort(h0);
}
__device__ __forceinline__ uint32_t bf16pack(float v0, float v1) {
    __nv_bfloat162 t = __floats2bfloat162_rn(v0, v1);
    return *(uint32_t*)&t;
}

// split-warp CSR row aggregation body: returns 8 partial sums for cols hl*8..hl*8+7
// (halves hf=0/1 each accumulate alternate edges; caller combines via shfl)
__device__ __forceinline__ void agg_row(const __half* __restrict__ xwh, int d, int N,
                                        int hf, int hl, float* acc)
{
    #pragma unroll
    for (int j = 0; j < 8; j++) acc[j] = 0.f;
    if (d >= N) return;

    float di = g_dinv[d];
    {   // self term (half 0 only)
        uint4 us = *(const uint4*)&xwh[(size_t)d * 128 + hl * 8];
        float2 a = __half22float2(*(__half2*)&us.x);
        float2 b = __half22float2(*(__half2*)&us.y);
        float2 c = __half22float2(*(__half2*)&us.z);
        float2 e = __half22float2(*(__half2*)&us.w);
        float m = hf ? 0.f : di * di;
        acc[0] = a.x * m; acc[1] = a.y * m; acc[2] = b.x * m; acc[3] = b.y * m;
        acc[4] = c.x * m; acc[5] = c.y * m; acc[6] = e.x * m; acc[7] = e.y * m;
    }

    int e0 = g_rowptr[d], e1 = g_rowptr[d + 1];
    int e = e0 + hf;
    int2 pA = (e < e1)     ? g_epack[e]     : make_int2(0, 0);
    int2 pB = (e + 2 < e1) ? g_epack[e + 2] : make_int2(0, 0);

    for (; e + 2 < e1; e += 4) {
        int en = e + 4;
        int2 qA = (en < e1)     ? g_epack[en]     : make_int2(0, 0);
        int2 qB = (en + 2 < e1) ? g_epack[en + 2] : make_int2(0, 0);

        float n0 = __int_as_float(pA.y);
        float n1 = __int_as_float(pB.y);
        uint4 u0 = *(const uint4*)&xwh[(size_t)pA.x * 128 + hl * 8];
        uint4 u1 = *(const uint4*)&xwh[(size_t)pB.x * 128 + hl * 8];
        float2 t;
        t = __half22float2(*(__half2*)&u0.x); acc[0] = fmaf(t.x, n0, acc[0]); acc[1] = fmaf(t.y, n0, acc[1]);
        t = __half22float2(*(__half2*)&u0.y); acc[2] = fmaf(t.x, n0, acc[2]); acc[3] = fmaf(t.y, n0, acc[3]);
        t = __half22float2(*(__half2*)&u0.z); acc[4] = fmaf(t.x, n0, acc[4]); acc[5] = fmaf(t.y, n0, acc[5]);
        t = __half22float2(*(__half2*)&u0.w); acc[6] = fmaf(t.x, n0, acc[6]); acc[7] = fmaf(t.y, n0, acc[7]);
        t = __half22float2(*(__half2*)&u1.x); acc[0] = fmaf(t.x, n1, acc[0]); acc[1] = fmaf(t.y, n1, acc[1]);
        t = __half22float2(*(__half2*)&u1.y); acc[2] = fmaf(t.x, n1, acc[2]); acc[3] = fmaf(t.y, n1, acc[3]);
        t = __half22float2(*(__half2*)&u1.z); acc[4] = fmaf(t.x, n1, acc[4]); acc[5] = fmaf(t.y, n1, acc[5]);
        t = __half22float2(*(__half2*)&u1.w); acc[6] = fmaf(t.x, n1, acc[6]); acc[7] = fmaf(t.y, n1, acc[7]);

        pA = qA; pB = qB;
    }
    if (e < e1) {
        float nm = __int_as_float(pA.y);
        uint4 u = *(const uint4*)&xwh[(size_t)pA.x * 128 + hl * 8];
        float2 t;
        t = __half22float2(*(__half2*)&u.x); acc[0] = fmaf(t.x, nm, acc[0]); acc[1] = fmaf(t.y, nm, acc[1]);
        t = __half22float2(*(__half2*)&u.y); acc[2] = fmaf(t.x, nm, acc[2]); acc[3] = fmaf(t.y, nm, acc[3]);
        t = __half22float2(*(__half2*)&u.z); acc[4] = fmaf(t.x, nm, acc[4]); acc[5] = fmaf(t.y, nm, acc[5]);
        t = __half22float2(*(__half2*)&u.w); acc[6] = fmaf(t.x, nm, acc[6]); acc[7] = fmaf(t.y, nm, acc[7]);
    }
}

// ---------------- degcnt ----------------
__global__ void degcnt_kernel(const int* __restrict__ dst, const int* __restrict__ batch,
                              int E, int N) {
    int i = blockIdx.x * blockDim.x + threadIdx.x;
    if (i < E) atomicAdd(&g_deg[dst[i]], 1);
    unsigned active = __ballot_sync(0xffffffffu, i < N);
    if (i < N) {
        int b = batch[i];
        unsigned m = __match_any_sync(active, b);
        int leader = __ffs(m) - 1;
        if ((threadIdx.x & 31) == leader)
            atomicAdd(&g_cnt[b], (float)__popc(m));
    }
}

// W -> bf16 mma fragment order.
__global__ void wsplit_kernel(const float* __restrict__ W1, const float* __restrict__ W2) {
    int i = blockIdx.x * blockDim.x + threadIdx.x;
    if (i >= 2 * 4096) return;
    int conv = i >> 12;
    int idx = i & 4095;
    int lane = idx & 31, nt = (idx >> 5) & 15, kk = idx >> 9;
    int g = lane >> 2, tg = lane & 3;
    int n = nt * 8 + g;
    int k0 = kk * 16 + 2 * tg;
    const float* W = conv ? W2 : W1;
    float v00 = W[(size_t)k0 * 128 + n];
    float v01 = W[(size_t)(k0 + 1) * 128 + n];
    float v10 = W[(size_t)(k0 + 8) * 128 + n];
    float v11 = W[(size_t)(k0 + 9) * 128 + n];
    float r00, r01, r10, r11;
    uint32_t bh0 = bf16pack_r(v00, v01, r00, r01);
    uint32_t bh1 = bf16pack_r(v10, v11, r10, r11);
    uint32_t bl0 = bf16pack(r00, r01);
    uint32_t bl1 = bf16pack(r10, r11);
    uint4 o = make_uint4(bh0, bh1, bl0, bl1);
    if (conv) g_wbuf2[idx] = o; else g_wbuf1[idx] = o;
}

// ---------------- scan (3-kernel, proven) ----------------
__global__ void scan1_kernel(int N) {
    int i = blockIdx.x * 256 + threadIdx.x;
    int v = (i < N) ? g_deg[i] : 0;
    int lane = threadIdx.x & 31, w = threadIdx.x >> 5;
    int s = v;
    #pragma unroll
    for (int o = 1; o < 32; o <<= 1) {
        int t = __shfl_up_sync(0xffffffffu, s, o);
        if (lane >= o) s += t;
    }
    __shared__ int wsum[8];
    if (lane == 31) wsum[w] = s;
    __syncthreads();
    if (w == 0) {
        int ss = (lane < 8) ? wsum[lane] : 0;
        #pragma unroll
        for (int o = 1; o < 8; o <<= 1) {
            int u = __shfl_up_sync(0xffffffffu, ss, o);
            if (lane >= o) ss += u;
        }
        if (lane < 8) wsum[lane] = ss;
    }
    __syncthreads();
    s += (w > 0) ? wsum[w - 1] : 0;
    if (i < N) g_scan[i] = s;
    if (threadIdx.x == 255) g_bsum[blockIdx.x] = s;
}

__global__ void scan2_kernel(int nb) {
    int t = threadIdx.x;
    int v = (t < nb) ? g_bsum[t] : 0;
    int lane = t & 31, w = t >> 5;
    int s = v;
    #pragma unroll
    for (int o = 1; o < 32; o <<= 1) {
        int u = __shfl_up_sync(0xffffffffu, s, o);
        if (lane >= o) s += u;
    }
    __shared__ int wsum[16];
    if (lane == 31) wsum[w] = s;
    __syncthreads();
    if (w == 0) {
        int ss = (lane < 16) ? wsum[lane] : 0;
        #pragma unroll
        for (int o = 1; o < 16; o <<= 1) {
            int u = __shfl_up_sync(0xffffffffu, ss, o);
            if (lane >= o) ss += u;
        }
        if (lane < 16) wsum[lane] = ss;
    }
    __syncthreads();
    s += (w > 0) ? wsum[w - 1] : 0;
    if (t < nb) g_boff[t] = s;
}

__global__ void scan3_kernel(int N) {
    int i = blockIdx.x * blockDim.x + threadIdx.x;
    if (i >= N) return;
    int b = i >> 8;
    int dv = g_deg[i];
    int incl = ((b > 0) ? g_boff[b - 1] : 0) + g_scan[i];
    g_rowptr[i + 1] = incl;
    g_cursor[i] = incl - dv;
    g_dinv[i] = rsqrtf((float)dv + 1.0f);
    g_deg[i] = 0;
    if (i == 0) g_rowptr[0] = 0;
}

__global__ void scatter_kernel(const int* __restrict__ src, const int* __restrict__ dst, int E) {
    int e = blockIdx.x * blockDim.x + threadIdx.x;
    if (e >= E) return;
    int d = dst[e];
    int s = src[e];
    int pos = atomicAdd(&g_cursor[d], 1);
    g_epack[pos] = make_int2(s, __float_as_int(g_dinv[s] * g_dinv[d]));
}

// ---------------- GEMM1 (R12-proven): Ch = fp16(A @ W), smem W, 2 CTAs/SM ----------------
static constexpr int SM_WS_BYTES = 4096 * 16;          // 65536
static constexpr int AS_STRIDE   = 148;
static constexpr int SM_GEMM_TOTAL = SM_WS_BYTES + 64 * AS_STRIDE * 4;  // 103424

__global__ __launch_bounds__(256, 2) void gemm_tc_kernel(
    const float* __restrict__ A, const uint4* __restrict__ Wbuf,
    __half* __restrict__ Ch, int M)
{
    extern __shared__ char smem[];
    uint4* Ws = (uint4*)smem;
    float* As = (float*)(smem + SM_WS_BYTES);
    uint32_t ws_b = smem_u32(Ws), as_b = smem_u32(As);

    int tid = threadIdx.x, wid = tid >> 5, lane = tid & 31;
    int g = lane >> 2, tg = lane & 3;
    int wm = wid & 1, wn = wid >> 1;
    int row0 = blockIdx.x * 64;

    #pragma unroll
    for (int it = 0; it < 16; it++) {
        int idx = it * 256 + tid;
        cp_async16(ws_b + idx * 16, Wbuf + idx, true);
    }
    #pragma unroll
    for (int kc = 0; kc < 4; kc++) {
        #pragma unroll
        for (int it = 0; it < 2; it++) {
            int j = it * 256 + tid;
            int r = j >> 3, c4 = j & 7;
            int col = kc * 32 + c4 * 4;
            bool pred = (row0 + r) < M;
            int r_eff = pred ? (row0 + r) : 0;
            cp_async16(as_b + (r * AS_STRIDE + col) * 4, A + (size_t)r_eff * 128 + col, pred);
        }
        cp_commit();
    }

    float acc[2][4][4];
    #pragma unroll
    for (int mi = 0; mi < 2; mi++)
        #pragma unroll
        for (int ni = 0; ni < 4; ni++)
            #pragma unroll
            for (int j = 0; j < 4; j++) acc[mi][ni][j] = 0.f;

    #pragma unroll
    for (int kc = 0; kc < 4; kc++) {
        if      (kc == 0) cp_wait_group<3>();
        else if (kc == 1) cp_wait_group<2>();
        else if (kc == 2) cp_wait_group<1>();
        else              cp_wait_group<0>();
        __syncthreads();

        #pragma unroll
        for (int k0 = 0; k0 < 2; k0++) {
            int kstep = kc * 2 + k0;
            int kb2 = kc * 32 + k0 * 16 + 2 * tg;
            uint32_t ah[2][4], al[2][4];
            #pragma unroll
            for (int mi = 0; mi < 2; mi++) {
                int r = wm * 32 + mi * 16 + g;
                float2 p0 = *(float2*)&As[r * AS_STRIDE + kb2];
                float2 p1 = *(float2*)&As[(r + 8) * AS_STRIDE + kb2];
                float2 p2 = *(float2*)&As[r * AS_STRIDE + kb2 + 8];
                float2 p3 = *(float2*)&As[(r + 8) * AS_STRIDE + kb2 + 8];
                float r0, r1;
                ah[mi][0] = bf16pack_r(p0.x, p0.y, r0, r1); al[mi][0] = bf16pack(r0, r1);
                ah[mi][1] = bf16pack_r(p1.x, p1.y, r0, r1); al[mi][1] = bf16pack(r0, r1);
                ah[mi][2] = bf16pack_r(p2.x, p2.y, r0, r1); al[mi][2] = bf16pack(r0, r1);
                ah[mi][3] = bf16pack_r(p3.x, p3.y, r0, r1); al[mi][3] = bf16pack(r0, r1);
            }
            #pragma unroll
            for (int ni = 0; ni < 4; ni++) {
                int nt = wn * 4 + ni;
                uint4 w4 = Ws[kstep * 512 + nt * 32 + lane];
                uint32_t bh[2] = { w4.x, w4.y };
                uint32_t bl[2] = { w4.z, w4.w };
                #pragma unroll
                for (int mi = 0; mi < 2; mi++) {
                    mma_bf16(acc[mi][ni], ah[mi], bh);
                    mma_bf16(acc[mi][ni], ah[mi], bl);
                    mma_bf16(acc[mi][ni], al[mi], bh);
                }
            }
        }
        __syncthreads();
    }

    #pragma unroll
    for (int mi = 0; mi < 2; mi++) {
        int r0 = row0 + wm * 32 + mi * 16 + g;
        int r1 = r0 + 8;
        #pragma unroll
        for (int ni = 0; ni < 4; ni++) {
            int col = wn * 32 + ni * 8 + tg * 2;
            if (r0 < M)
                *(__half2*)&Ch[(size_t)r0 * 128 + col] = __floats2half2_rn(acc[mi][ni][0], acc[mi][ni][1]);
            if (r1 < M)
                *(__half2*)&Ch[(size_t)r1 * 128 + col] = __floats2half2_rn(acc[mi][ni][2], acc[mi][ni][3]);
        }
    }
}

// ---------------- FUSED conv1-aggregate + GEMM2: xwh2 = fp16(relu(agg(xwh)+b1) @ W2) ------
__global__ __launch_bounds__(256, 2) void agg_gemm_kernel(
    const __half* __restrict__ xwh, const float* __restrict__ bias,
    const uint4* __restrict__ Wbuf, __half* __restrict__ Ch, int N)
{
    extern __shared__ char smem[];
    uint4* Ws = (uint4*)smem;
    float* As = (float*)(smem + SM_WS_BYTES);
    uint32_t ws_b = smem_u32(Ws);

    int tid = threadIdx.x, wid = tid >> 5, lane = tid & 31;
    int g = lane >> 2, tg = lane & 3;
    int wm = wid & 1, wn = wid >> 1;
    int hf = lane >> 4, hl = lane & 15;
    int row0 = blockIdx.x * 64;

    // kick off W tile loads; they overlap the whole aggregation phase
    #pragma unroll
    for (int it = 0; it < 16; it++) {
        int idx = it * 256 + tid;
        cp_async16(ws_b + idx * 16, Wbuf + idx, true);
    }
    cp_commit();

    // ---- phase 1: aggregate 8 rows per warp into smem A-tile (h = relu(agg + b1)) ----
    float4 bia0 = *(const float4*)&bias[hl * 8];
    float4 bia1 = *(const float4*)&bias[hl * 8 + 4];
    #pragma unroll 1
    for (int i = 0; i < 8; i++) {
        int r_local = wid * 8 + i;
        int d = row0 + r_local;
        float acc[8];
        agg_row(xwh, d, N, hf, hl, acc);
        #pragma unroll
        for (int j = 0; j < 8; j++)
            acc[j] += __shfl_down_sync(0xffffffffu, acc[j], 16);
        if (hf == 0) {
            float4 o0, o1;
            if (d < N) {
                o0 = make_float4(fmaxf(acc[0] + bia0.x, 0.f), fmaxf(acc[1] + bia0.y, 0.f),
                                 fmaxf(acc[2] + bia0.z, 0.f), fmaxf(acc[3] + bia0.w, 0.f));
                o1 = make_float4(fmaxf(acc[4] + bia1.x, 0.f), fmaxf(acc[5] + bia1.y, 0.f),
                                 fmaxf(acc[6] + bia1.z, 0.f), fmaxf(acc[7] + bia1.w, 0.f));
            } else {
                o0 = make_float4(0.f, 0.f, 0.f, 0.f);
                o1 = o0;
            }
            *(float4*)&As[r_local * AS_STRIDE + hl * 8]     = o0;
            *(float4*)&As[r_local * AS_STRIDE + hl * 8 + 4] = o1;
        }
    }
    cp_wait_group<0>();
    __syncthreads();

    // ---- phase 2: GEMM on the smem A-tile ----
    float acc2[2][4][4];
    #pragma unroll
    for (int mi = 0; mi < 2; mi++)
        #pragma unroll
        for (int ni = 0; ni < 4; ni++)
            #pragma unroll
            for (int j = 0; j < 4; j++) acc2[mi][ni][j] = 0.f;

    #pragma unroll
    for (int kc = 0; kc < 4; kc++) {
        #pragma unroll
        for (int k0 = 0; k0 < 2; k0++) {
            int kstep = kc * 2 + k0;
            int kb2 = kc * 32 + k0 * 16 + 2 * tg;
            uint32_t ah[2][4], al[2][4];
            #pragma unroll
            for (int mi = 0; mi < 2; mi++) {
                int r = wm * 32 + mi * 16 + g;
                float2 p0 = *(float2*)&As[r * AS_STRIDE + kb2];
                float2 p1 = *(float2*)&As[(r + 8) * AS_STRIDE + kb2];
                float2 p2 = *(float2*)&As[r * AS_STRIDE + kb2 + 8];
                float2 p3 = *(float2*)&As[(r + 8) * AS_STRIDE + kb2 + 8];
                float r0, r1;
                ah[mi][0] = bf16pack_r(p0.x, p0.y, r0, r1); al[mi][0] = bf16pack(r0, r1);
                ah[mi][1] = bf16pack_r(p1.x, p1.y, r0, r1); al[mi][1] = bf16pack(r0, r1);
                ah[mi][2] = bf16pack_r(p2.x, p2.y, r0, r1); al[mi][2] = bf16pack(r0, r1);
                ah[mi][3] = bf16pack_r(p3.x, p3.y, r0, r1); al[mi][3] = bf16pack(r0, r1);
            }
            #pragma unroll
            for (int ni = 0; ni < 4; ni++) {
                int nt = wn * 4 + ni;
                uint4 w4 = Ws[kstep * 512 + nt * 32 + lane];
                uint32_t bh[2] = { w4.x, w4.y };
                uint32_t bl[2] = { w4.z, w4.w };
                #pragma unroll
                for (int mi = 0; mi < 2; mi++) {
                    mma_bf16(acc2[mi][ni], ah[mi], bh);
                    mma_bf16(acc2[mi][ni], ah[mi], bl);
                    mma_bf16(acc2[mi][ni], al[mi], bh);
                }
            }
        }
    }

    #pragma unroll
    for (int mi = 0; mi < 2; mi++) {
        int r0 = row0 + wm * 32 + mi * 16 + g;
        int r1 = r0 + 8;
        #pragma unroll
        for (int ni = 0; ni < 4; ni++) {
            int col = wn * 32 + ni * 8 + tg * 2;
            if (r0 < N)
                *(__half2*)&Ch[(size_t)r0 * 128 + col] = __floats2half2_rn(acc2[mi][ni][0], acc2[mi][ni][1]);
            if (r1 < N)
                *(__half2*)&Ch[(size_t)r1 * 128 + col] = __floats2half2_rn(acc2[mi][ni][2], acc2[mi][ni][3]);
        }
    }
}

// ---------------- conv2 aggregate + pool (standalone, reads xwh2) ------------------------
__global__ void agg_pool_kernel(const __half* __restrict__ xwh, const float* __restrict__ bias,
                                const int* __restrict__ batch, int N)
{
    int d = (blockIdx.x * blockDim.x + threadIdx.x) >> 5;
    int lane = threadIdx.x & 31;
    if (d >= N) return;
    int hf = lane >> 4, hl = lane & 15;

    float acc[8];
    agg_row(xwh, d, N, hf, hl, acc);
    #pragma unroll
    for (int j = 0; j < 8; j++)
        acc[j] += __shfl_down_sync(0xffffffffu, acc[j], 16);

    if (hf == 0) {
        float4 b0 = *(const float4*)&bias[hl * 8];
        float4 b1 = *(const float4*)&bias[hl * 8 + 4];
        float4 o0 = make_float4(acc[0] + b0.x, acc[1] + b0.y, acc[2] + b0.z, acc[3] + b0.w);
        float4 o1 = make_float4(acc[4] + b1.x, acc[5] + b1.y, acc[6] + b1.z, acc[7] + b1.w);
        int gi = batch[d];
        red_add_v4(&g_sums[(size_t)gi * 128 + hl * 8], o0);
        red_add_v4(&g_sums[(size_t)gi * 128 + hl * 8 + 4], o1);
    }
}

// ---------------- GRU step (h0=0) + relu + layernorm + linear head; self-cleans sums/cnt --
__global__ __launch_bounds__(128) void gru_ln_out_kernel(
    const float* __restrict__ W_ih, const float* __restrict__ b_ih,
    const float* __restrict__ b_hh, const float* __restrict__ W_lin,
    const float* __restrict__ b_lin, float* __restrict__ out)
{
    int g = blockIdx.x;
    int tid = threadIdx.x;
    int lane = tid & 31, w = tid >> 5;

    __shared__ float gs[128];
    __shared__ float gi[384];
    __shared__ float rbuf1[4], rbuf2[4];

    float cnt = fmaxf(g_cnt[g], 1.0f);
    gs[tid] = g_sums[(size_t)g * 128 + tid] / cnt;
    g_sums[(size_t)g * 128 + tid] = 0.f;
    if (tid == 0) g_cnt[g] = 0.f;
    __syncthreads();

    for (int j = w; j < 384; j += 4) {
        const float* wr = W_ih + (size_t)j * 128;
        float s = 0.f;
        #pragma unroll
        for (int t = 0; t < 4; t++) {
            int k = lane + t * 32;
            s += gs[k] * wr[k];
        }
        #pragma unroll
        for (int o = 16; o > 0; o >>= 1) s += __shfl_xor_sync(0xffffffffu, s, o);
        if (lane == 0) gi[j] = s + b_ih[j];
    }
    __syncthreads();

    float r  = 1.f / (1.f + expf(-(gi[tid]       + b_hh[tid])));
    float z  = 1.f / (1.f + expf(-(gi[tid + 128] + b_hh[tid + 128])));
    float nn = tanhf(gi[tid + 256] + r * b_hh[tid + 256]);
    float v  = fmaxf((1.f - z) * nn, 0.f);

    float s1 = v, s2 = v * v;
    #pragma unroll
    for (int o = 16; o > 0; o >>= 1) {
        s1 += __shfl_xor_sync(0xffffffffu, s1, o);
        s2 += __shfl_xor_sync(0xffffffffu, s2, o);
    }
    if (lane == 0) { rbuf1[w] = s1; rbuf2[w] = s2; }
    __syncthreads();
    float S1 = rbuf1[0] + rbuf1[1] + rbuf1[2] + rbuf1[3];
    float S2 = rbuf2[0] + rbuf2[1] + rbuf2[2] + rbuf2[3];
    float mu  = S1 * (1.f / 128.f);
    float var = S2 * (1.f / 128.f) - mu * mu;
    float y = (v - mu) * rsqrtf(var + 1e-5f);

    float p = y * W_lin[tid];
    #pragma unroll
    for (int o = 16; o > 0; o >>= 1) p += __shfl_xor_sync(0xffffffffu, p, o);
    __syncthreads();
    if (lane == 0) rbuf1[w] = p;
    __syncthreads();
    if (tid == 0) out[g] = rbuf1[0] + rbuf1[1] + rbuf1[2] + rbuf1[3] + b_lin[0];
}

// ---------------- launch ----------------
extern "C" void kernel_launch(void* const* d_in, const int* in_sizes, int n_in,
                              void* d_out, int out_size)
{
    const float* x     = (const float*)d_in[0];
    const int*   ei    = (const int*)  d_in[1];
    const int*   batch = (const int*)  d_in[2];
    const float* W1    = (const float*)d_in[3];
    const float* b1    = (const float*)d_in[4];
    const float* W2    = (const float*)d_in[5];
    const float* b2    = (const float*)d_in[6];
    const float* W_ih  = (const float*)d_in[7];
    /* W_hh = d_in[8] unused: h0 == 0 */
    const float* b_ih  = (const float*)d_in[9];
    const float* b_hh  = (const float*)d_in[10];
    const float* W_lin = (const float*)d_in[11];
    const float* b_lin = (const float*)d_in[12];
    float* out = (float*)d_out;

    const int N = in_sizes[0] / 128;
    const int E = in_sizes[1] / 2;
    const int G = out_size;
    const int* srcp = ei;
    const int* dstp = ei + E;

    __half *p_xwh, *p_xwh2;
    uint4  *p_wb1, *p_wb2;
    cudaGetSymbolAddress((void**)&p_xwh,  g_xwh);
    cudaGetSymbolAddress((void**)&p_xwh2, g_xwh2);
    cudaGetSymbolAddress((void**)&p_wb1,  g_wbuf1);
    cudaGetSymbolAddress((void**)&p_wb2,  g_wbuf2);

    static cudaStream_t s_side = nullptr;
    static cudaEvent_t ev_fork = nullptr, ev_join = nullptr;
    if (!s_side) {
        cudaFuncSetAttribute(gemm_tc_kernel,
                             cudaFuncAttributeMaxDynamicSharedMemorySize, SM_GEMM_TOTAL);
        cudaFuncSetAttribute(agg_gemm_kernel,
                             cudaFuncAttributeMaxDynamicSharedMemorySize, SM_GEMM_TOTAL);
        cudaStreamCreateWithFlags(&s_side, cudaStreamNonBlocking);
        cudaEventCreateWithFlags(&ev_fork, cudaEventDisableTiming);
        cudaEventCreateWithFlags(&ev_join, cudaEventDisableTiming);
    }

    const int T = 256;
    int bN   = (N + T - 1) / T;
    int bE   = (E + T - 1) / T;
    int nb   = (N + 255) / 256;
    long long wthreads = (long long)N * 32;
    int bAgg = (int)((wthreads + T - 1) / T);
    int bGemm = (N + 63) / 64;

    // fork: CSR build on side stream, GEMM path on main stream
    cudaEventRecord(ev_fork, 0);
    cudaStreamWaitEvent(s_side, ev_fork, 0);

    // submission slots: wsplit(1), degcnt(2), scan1(3), gemm1(4) <- ncu control
    wsplit_kernel<<<(2 * 4096 + T - 1) / T, T>>>(W1, W2);              // main
    degcnt_kernel<<<bE, T, 0, s_side>>>(dstp, batch, E, N);            // side
    scan1_kernel<<<nb, 256, 0, s_side>>>(N);                           // side
    gemm_tc_kernel<<<bGemm, 256, SM_GEMM_TOTAL>>>(x, p_wb1, p_xwh, N); // main <- ncu slot 4
    scan2_kernel<<<1, 512, 0, s_side>>>(nb);                           // side
    scan3_kernel<<<bN, T, 0, s_side>>>(N);                             // side
    scatter_kernel<<<bE, T, 0, s_side>>>(srcp, dstp, E);               // side
    cudaEventRecord(ev_join, s_side);

    cudaStreamWaitEvent(0, ev_join, 0);

    // fused conv1-aggregate + GEMM2, then conv2 aggregate + pool
    agg_gemm_kernel<<<bGemm, 256, SM_GEMM_TOTAL>>>(p_xwh, b1, p_wb2, p_xwh2, N);
    agg_pool_kernel<<<bAgg, T>>>(p_xwh2, b2, batch, N);

    // GRU + LN + head (self-cleans g_sums/g_cnt)
    gru_ln_out_kernel<<<G, 128>>>(W_ih, b_ih, b_hh, W_lin, b_lin, out);
}

// round 15
// speedup vs baseline: 1.1674x; 1.1674x over previous
#include <cuda_runtime.h>
#include <cuda_bf16.h>
#include <cuda_fp16.h>
#include <math.h>
#include <stdint.h>

#define NODES_MAX 100000
#define EDGES_MAX 1600000
#define GRAPHS_MAX 2048

// ---------------- scratch (no allocations allowed) ----------------
__device__ __half g_xwh [NODES_MAX * 128];   // x @ W as fp16 rows (gather + self)
__device__ float  g_h   [NODES_MAX * 128];   // hidden after conv1 (fp32, GEMM2 input)
__device__ float  g_dinv[NODES_MAX];         // rsqrt(deg+1)
__device__ float  g_sums[GRAPHS_MAX * 128];  // pooled sums (self-cleaned by gru)
__device__ float  g_cnt [GRAPHS_MAX];        // nodes per graph (self-cleaned by gru)
__device__ uint2  g_wbuf1[4096];             // W1 fp16 fragment order {h0h1(k0,k0+1), h0h1(k8,k9)}
__device__ uint2  g_wbuf2[4096];             // W2 likewise
// CSR build
__device__ int    g_deg   [NODES_MAX];       // self-cleaned by scan3
__device__ int    g_scan  [NODES_MAX];
__device__ int    g_bsum  [1024];
__device__ int    g_boff  [1024];
__device__ int    g_rowptr[NODES_MAX + 1];
__device__ int    g_cursor[NODES_MAX];
__device__ int2   g_epack [EDGES_MAX];       // {src, bits(dinv[src]*dinv[dst])} sorted by dst

// ---------------- helpers ----------------
__device__ __forceinline__ void red_add_v4(float* addr, float4 v) {
    asm volatile("red.global.add.v4.f32 [%0], {%1,%2,%3,%4};"
                 :: "l"(addr), "f"(v.x), "f"(v.y), "f"(v.z), "f"(v.w) : "memory");
}
__device__ __forceinline__ void mma_f16(float* c, const uint32_t* a, const uint32_t* b) {
    asm volatile(
        "mma.sync.aligned.m16n8k16.row.col.f32.f16.f16.f32 "
        "{%0,%1,%2,%3},{%4,%5,%6,%7},{%8,%9},{%0,%1,%2,%3};"
        : "+f"(c[0]), "+f"(c[1]), "+f"(c[2]), "+f"(c[3])
        : "r"(a[0]), "r"(a[1]), "r"(a[2]), "r"(a[3]), "r"(b[0]), "r"(b[1]));
}
__device__ __forceinline__ uint32_t smem_u32(const void* p) {
    uint32_t a;
    asm("{ .reg .u64 t; cvta.to.shared.u64 t, %1; cvt.u32.u64 %0, t; }" : "=r"(a) : "l"(p));
    return a;
}
__device__ __forceinline__ void cp_async16(uint32_t dst, const void* src, bool pred) {
    int sz = pred ? 16 : 0;
    asm volatile("cp.async.cg.shared.global [%0], [%1], 16, %2;"
                 :: "r"(dst), "l"(src), "r"(sz) : "memory");
}
__device__ __forceinline__ void cp_commit() {
    asm volatile("cp.async.commit_group;" ::: "memory");
}
template <int NW>
__device__ __forceinline__ void cp_wait_group() {
    asm volatile("cp.async.wait_group %0;" :: "n"(NW) : "memory");
}
__device__ __forceinline__ uint32_t f16pack(float v0, float v1) {
    __half2 t = __floats2half2_rn(v0, v1);
    return *(uint32_t*)&t;
}

// ---------------- degcnt: deg histogram (random dst) + warp-aggregated cnt (sorted batch) -
__global__ void degcnt_kernel(const int* __restrict__ dst, const int* __restrict__ batch,
                              int E, int N) {
    int i = blockIdx.x * blockDim.x + threadIdx.x;
    if (i < E) atomicAdd(&g_deg[dst[i]], 1);
    unsigned active = __ballot_sync(0xffffffffu, i < N);
    if (i < N) {
        int b = batch[i];
        unsigned m = __match_any_sync(active, b);
        int leader = __ffs(m) - 1;
        if ((threadIdx.x & 31) == leader)
            atomicAdd(&g_cnt[b], (float)__popc(m));
    }
}

// W -> fp16 mma fragment order (single term).
__global__ void wsplit_kernel(const float* __restrict__ W1, const float* __restrict__ W2) {
    int i = blockIdx.x * blockDim.x + threadIdx.x;
    if (i >= 2 * 4096) return;
    int conv = i >> 12;
    int idx = i & 4095;
    int lane = idx & 31, nt = (idx >> 5) & 15, kk = idx >> 9;   // kk 0..7
    int g = lane >> 2, tg = lane & 3;
    int n = nt * 8 + g;
    int k0 = kk * 16 + 2 * tg;
    const float* W = conv ? W2 : W1;
    float v00 = W[(size_t)k0 * 128 + n];
    float v01 = W[(size_t)(k0 + 1) * 128 + n];
    float v10 = W[(size_t)(k0 + 8) * 128 + n];
    float v11 = W[(size_t)(k0 + 9) * 128 + n];
    uint2 o = make_uint2(f16pack(v00, v01), f16pack(v10, v11));
    if (conv) g_wbuf2[idx] = o; else g_wbuf1[idx] = o;
}

// ---------------- scan (3-kernel, proven) ----------------
__global__ void scan1_kernel(int N) {
    int i = blockIdx.x * 256 + threadIdx.x;
    int v = (i < N) ? g_deg[i] : 0;
    int lane = threadIdx.x & 31, w = threadIdx.x >> 5;
    int s = v;
    #pragma unroll
    for (int o = 1; o < 32; o <<= 1) {
        int t = __shfl_up_sync(0xffffffffu, s, o);
        if (lane >= o) s += t;
    }
    __shared__ int wsum[8];
    if (lane == 31) wsum[w] = s;
    __syncthreads();
    if (w == 0) {
        int ss = (lane < 8) ? wsum[lane] : 0;
        #pragma unroll
        for (int o = 1; o < 8; o <<= 1) {
            int u = __shfl_up_sync(0xffffffffu, ss, o);
            if (lane >= o) ss += u;
        }
        if (lane < 8) wsum[lane] = ss;
    }
    __syncthreads();
    s += (w > 0) ? wsum[w - 1] : 0;
    if (i < N) g_scan[i] = s;
    if (threadIdx.x == 255) g_bsum[blockIdx.x] = s;
}

__global__ void scan2_kernel(int nb) {
    int t = threadIdx.x;                     // 512 threads
    int v = (t < nb) ? g_bsum[t] : 0;
    int lane = t & 31, w = t >> 5;
    int s = v;
    #pragma unroll
    for (int o = 1; o < 32; o <<= 1) {
        int u = __shfl_up_sync(0xffffffffu, s, o);
        if (lane >= o) s += u;
    }
    __shared__ int wsum[16];
    if (lane == 31) wsum[w] = s;
    __syncthreads();
    if (w == 0) {
        int ss = (lane < 16) ? wsum[lane] : 0;
        #pragma unroll
        for (int o = 1; o < 16; o <<= 1) {
            int u = __shfl_up_sync(0xffffffffu, ss, o);
            if (lane >= o) ss += u;
        }
        if (lane < 16) wsum[lane] = ss;
    }
    __syncthreads();
    s += (w > 0) ? wsum[w - 1] : 0;
    if (t < nb) g_boff[t] = s;
}

__global__ void scan3_kernel(int N) {
    int i = blockIdx.x * blockDim.x + threadIdx.x;
    if (i >= N) return;
    int b = i >> 8;
    int dv = g_deg[i];
    int incl = ((b > 0) ? g_boff[b - 1] : 0) + g_scan[i];
    g_rowptr[i + 1] = incl;
    g_cursor[i] = incl - dv;
    g_dinv[i] = rsqrtf((float)dv + 1.0f);
    g_deg[i] = 0;                            // self-clean for next call
    if (i == 0) g_rowptr[0] = 0;
}

__global__ void scatter_kernel(const int* __restrict__ src, const int* __restrict__ dst, int E) {
    int e = blockIdx.x * blockDim.x + threadIdx.x;
    if (e >= E) return;
    int d = dst[e];
    int s = src[e];
    int pos = atomicAdd(&g_cursor[d], 1);
    g_epack[pos] = make_int2(s, __float_as_int(g_dinv[s] * g_dinv[d]));
}

// ---------------- tensor GEMM: Ch[M,128] = fp16(A[M,128] @ W), single-term fp16 ----------
// smem: Ws 32KB + A-tile 37.9KB = 70.7KB -> 3 CTAs/SM.
static constexpr int SM_WS_BYTES = 4096 * 8;           // 32768
static constexpr int AS_STRIDE   = 148;                // floats; 148 % 32 = 20 -> <=2-way
static constexpr int SM_GEMM_TOTAL = SM_WS_BYTES + 64 * AS_STRIDE * 4;  // 70656

__global__ __launch_bounds__(256, 3) void gemm_tc_kernel(
    const float* __restrict__ A, const uint2* __restrict__ Wbuf,
    __half* __restrict__ Ch, int M)
{
    extern __shared__ char smem[];
    uint2* Ws = (uint2*)smem;
    float* As = (float*)(smem + SM_WS_BYTES);
    uint32_t ws_b = smem_u32(Ws), as_b = smem_u32(As);

    int tid = threadIdx.x, wid = tid >> 5, lane = tid & 31;
    int g = lane >> 2, tg = lane & 3;
    int wm = wid & 1, wn = wid >> 1;         // warp tile: m32 x n32
    int row0 = blockIdx.x * 64;

    // W: 32768 bytes = 2048 x 16B, 8 per thread (group 0 with A chunk 0)
    #pragma unroll
    for (int it = 0; it < 8; it++) {
        int idx = it * 256 + tid;
        cp_async16(ws_b + idx * 16, (const char*)Wbuf + idx * 16, true);
    }
    // A chunks: per kc, 512 float4 (64 rows x 8 float4)
    #pragma unroll
    for (int kc = 0; kc < 4; kc++) {
        #pragma unroll
        for (int it = 0; it < 2; it++) {
            int j = it * 256 + tid;          // 0..511
            int r = j >> 3, c4 = j & 7;
            int col = kc * 32 + c4 * 4;
            bool pred = (row0 + r) < M;
            int r_eff = pred ? (row0 + r) : 0;
            cp_async16(as_b + (r * AS_STRIDE + col) * 4, A + (size_t)r_eff * 128 + col, pred);
        }
        cp_commit();                          // groups: G0=W+A0, G1=A1, G2=A2, G3=A3
    }

    float acc[2][4][4];
    #pragma unroll
    for (int mi = 0; mi < 2; mi++)
        #pragma unroll
        for (int ni = 0; ni < 4; ni++)
            #pragma unroll
            for (int j = 0; j < 4; j++) acc[mi][ni][j] = 0.f;

    #pragma unroll
    for (int kc = 0; kc < 4; kc++) {
        if      (kc == 0) cp_wait_group<3>();
        else if (kc == 1) cp_wait_group<2>();
        else if (kc == 2) cp_wait_group<1>();
        else              cp_wait_group<0>();
        __syncthreads();

        #pragma unroll
        for (int k0 = 0; k0 < 2; k0++) {
            int kstep = kc * 2 + k0;
            int kb2 = kc * 32 + k0 * 16 + 2 * tg;
            uint32_t ah[2][4];
            #pragma unroll
            for (int mi = 0; mi < 2; mi++) {
                int r = wm * 32 + mi * 16 + g;
                float2 p0 = *(float2*)&As[r * AS_STRIDE + kb2];
                float2 p1 = *(float2*)&As[(r + 8) * AS_STRIDE + kb2];
                float2 p2 = *(float2*)&As[r * AS_STRIDE + kb2 + 8];
                float2 p3 = *(float2*)&As[(r + 8) * AS_STRIDE + kb2 + 8];
                ah[mi][0] = f16pack(p0.x, p0.y);
                ah[mi][1] = f16pack(p1.x, p1.y);
                ah[mi][2] = f16pack(p2.x, p2.y);
                ah[mi][3] = f16pack(p3.x, p3.y);
            }
            #pragma unroll
            for (int ni = 0; ni < 4; ni++) {
                int nt = wn * 4 + ni;
                uint2 w2 = Ws[kstep * 512 + nt * 32 + lane];
                uint32_t bh[2] = { w2.x, w2.y };
                #pragma unroll
                for (int mi = 0; mi < 2; mi++)
                    mma_f16(acc[mi][ni], ah[mi], bh);
            }
        }
        __syncthreads();
    }

    #pragma unroll
    for (int mi = 0; mi < 2; mi++) {
        int r0 = row0 + wm * 32 + mi * 16 + g;
        int r1 = r0 + 8;
        #pragma unroll
        for (int ni = 0; ni < 4; ni++) {
            int col = wn * 32 + ni * 8 + tg * 2;
            if (r0 < M)
                *(__half2*)&Ch[(size_t)r0 * 128 + col] = __floats2half2_rn(acc[mi][ni][0], acc[mi][ni][1]);
            if (r1 < M)
                *(__half2*)&Ch[(size_t)r1 * 128 + col] = __floats2half2_rn(acc[mi][ni][2], acc[mi][ni][3]);
        }
    }
}

// ---------------- CSR aggregation (split-warp + epack software prefetch) ------------------
template <bool POOL>
__global__ void agg_kernel(const __half* __restrict__ xwh, const float* __restrict__ bias,
                           float* __restrict__ hout, const int* __restrict__ batch, int N)
{
    int d = (blockIdx.x * blockDim.x + threadIdx.x) >> 5;
    int lane = threadIdx.x & 31;
    if (d >= N) return;
    int hf = lane >> 4, hl = lane & 15;        // half-warp id, lane within half

    float di = g_dinv[d];
    float sl = di * di;

    float acc[8];
    {   // self term (half 0 only; half 1 starts at zero)
        uint4 us = *(const uint4*)&xwh[(size_t)d * 128 + hl * 8];
        float2 a = __half22float2(*(__half2*)&us.x);
        float2 b = __half22float2(*(__half2*)&us.y);
        float2 c = __half22float2(*(__half2*)&us.z);
        float2 e = __half22float2(*(__half2*)&us.w);
        float m = hf ? 0.f : sl;
        acc[0] = a.x * m; acc[1] = a.y * m; acc[2] = b.x * m; acc[3] = b.y * m;
        acc[4] = c.x * m; acc[5] = c.y * m; acc[6] = e.x * m; acc[7] = e.y * m;
    }

    int e0 = g_rowptr[d], e1 = g_rowptr[d + 1];
    int e = e0 + hf;                            // halves interleave edges
    int2 pA = (e < e1)     ? g_epack[e]     : make_int2(0, 0);
    int2 pB = (e + 2 < e1) ? g_epack[e + 2] : make_int2(0, 0);

    for (; e + 2 < e1; e += 4) {
        int en = e + 4;
        int2 qA = (en < e1)     ? g_epack[en]     : make_int2(0, 0);
        int2 qB = (en + 2 < e1) ? g_epack[en + 2] : make_int2(0, 0);

        float n0 = __int_as_float(pA.y);
        float n1 = __int_as_float(pB.y);
        uint4 u0 = *(const uint4*)&xwh[(size_t)pA.x * 128 + hl * 8];
        uint4 u1 = *(const uint4*)&xwh[(size_t)pB.x * 128 + hl * 8];
        float2 t;
        t = __half22float2(*(__half2*)&u0.x); acc[0] = fmaf(t.x, n0, acc[0]); acc[1] = fmaf(t.y, n0, acc[1]);
        t = __half22float2(*(__half2*)&u0.y); acc[2] = fmaf(t.x, n0, acc[2]); acc[3] = fmaf(t.y, n0, acc[3]);
        t = __half22float2(*(__half2*)&u0.z); acc[4] = fmaf(t.x, n0, acc[4]); acc[5] = fmaf(t.y, n0, acc[5]);
        t = __half22float2(*(__half2*)&u0.w); acc[6] = fmaf(t.x, n0, acc[6]); acc[7] = fmaf(t.y, n0, acc[7]);
        t = __half22float2(*(__half2*)&u1.x); acc[0] = fmaf(t.x, n1, acc[0]); acc[1] = fmaf(t.y, n1, acc[1]);
        t = __half22float2(*(__half2*)&u1.y); acc[2] = fmaf(t.x, n1, acc[2]); acc[3] = fmaf(t.y, n1, acc[3]);
        t = __half22float2(*(__half2*)&u1.z); acc[4] = fmaf(t.x, n1, acc[4]); acc[5] = fmaf(t.y, n1, acc[5]);
        t = __half22float2(*(__half2*)&u1.w); acc[6] = fmaf(t.x, n1, acc[6]); acc[7] = fmaf(t.y, n1, acc[7]);

        pA = qA; pB = qB;
    }
    if (e < e1) {
        float nm = __int_as_float(pA.y);
        uint4 u = *(const uint4*)&xwh[(size_t)pA.x * 128 + hl * 8];
        float2 t;
        t = __half22float2(*(__half2*)&u.x); acc[0] = fmaf(t.x, nm, acc[0]); acc[1] = fmaf(t.y, nm, acc[1]);
        t = __half22float2(*(__half2*)&u.y); acc[2] = fmaf(t.x, nm, acc[2]); acc[3] = fmaf(t.y, nm, acc[3]);
        t = __half22float2(*(__half2*)&u.z); acc[4] = fmaf(t.x, nm, acc[4]); acc[5] = fmaf(t.y, nm, acc[5]);
        t = __half22float2(*(__half2*)&u.w); acc[6] = fmaf(t.x, nm, acc[6]); acc[7] = fmaf(t.y, nm, acc[7]);
    }

    #pragma unroll
    for (int j = 0; j < 8; j++)
        acc[j] += __shfl_down_sync(0xffffffffu, acc[j], 16);

    if (hf == 0) {
        float4 b0 = *(const float4*)&bias[hl * 8];
        float4 b1 = *(const float4*)&bias[hl * 8 + 4];
        float4 o0 = make_float4(acc[0] + b0.x, acc[1] + b0.y, acc[2] + b0.z, acc[3] + b0.w);
        float4 o1 = make_float4(acc[4] + b1.x, acc[5] + b1.y, acc[6] + b1.z, acc[7] + b1.w);
        if (POOL) {
            int gi = batch[d];
            red_add_v4(&g_sums[(size_t)gi * 128 + hl * 8], o0);
            red_add_v4(&g_sums[(size_t)gi * 128 + hl * 8 + 4], o1);
        } else {
            o0.x = fmaxf(o0.x, 0.f); o0.y = fmaxf(o0.y, 0.f);
            o0.z = fmaxf(o0.z, 0.f); o0.w = fmaxf(o0.w, 0.f);
            o1.x = fmaxf(o1.x, 0.f); o1.y = fmaxf(o1.y, 0.f);
            o1.z = fmaxf(o1.z, 0.f); o1.w = fmaxf(o1.w, 0.f);
            *(float4*)&hout[(size_t)d * 128 + hl * 8]     = o0;
            *(float4*)&hout[(size_t)d * 128 + hl * 8 + 4] = o1;
        }
    }
}

// ---------------- GRU step (h0=0) + relu + layernorm + linear head; self-cleans sums/cnt --
__global__ __launch_bounds__(128) void gru_ln_out_kernel(
    const float* __restrict__ W_ih, const float* __restrict__ b_ih,
    const float* __restrict__ b_hh, const float* __restrict__ W_lin,
    const float* __restrict__ b_lin, float* __restrict__ out)
{
    int g = blockIdx.x;
    int tid = threadIdx.x;
    int lane = tid & 31, w = tid >> 5;

    __shared__ float gs[128];
    __shared__ float gi[384];
    __shared__ float rbuf1[4], rbuf2[4];

    float cnt = fmaxf(g_cnt[g], 1.0f);
    gs[tid] = g_sums[(size_t)g * 128 + tid] / cnt;
    g_sums[(size_t)g * 128 + tid] = 0.f;     // self-clean for next call
    if (tid == 0) g_cnt[g] = 0.f;
    __syncthreads();

    for (int j = w; j < 384; j += 4) {
        const float* wr = W_ih + (size_t)j * 128;
        float s = 0.f;
        #pragma unroll
        for (int t = 0; t < 4; t++) {
            int k = lane + t * 32;
            s += gs[k] * wr[k];
        }
        #pragma unroll
        for (int o = 16; o > 0; o >>= 1) s += __shfl_xor_sync(0xffffffffu, s, o);
        if (lane == 0) gi[j] = s + b_ih[j];
    }
    __syncthreads();

    float r  = 1.f / (1.f + expf(-(gi[tid]       + b_hh[tid])));
    float z  = 1.f / (1.f + expf(-(gi[tid + 128] + b_hh[tid + 128])));
    float nn = tanhf(gi[tid + 256] + r * b_hh[tid + 256]);
    float v  = fmaxf((1.f - z) * nn, 0.f);

    float s1 = v, s2 = v * v;
    #pragma unroll
    for (int o = 16; o > 0; o >>= 1) {
        s1 += __shfl_xor_sync(0xffffffffu, s1, o);
        s2 += __shfl_xor_sync(0xffffffffu, s2, o);
    }
    if (lane == 0) { rbuf1[w] = s1; rbuf2[w] = s2; }
    __syncthreads();
    float S1 = rbuf1[0] + rbuf1[1] + rbuf1[2] + rbuf1[3];
    float S2 = rbuf2[0] + rbuf2[1] + rbuf2[2] + rbuf2[3];
    float mu  = S1 * (1.f / 128.f);
    float var = S2 * (1.f / 128.f) - mu * mu;
    float y = (v - mu) * rsqrtf(var + 1e-5f);

    float p = y * W_lin[tid];
    #pragma unroll
    for (int o = 16; o > 0; o >>= 1) p += __shfl_xor_sync(0xffffffffu, p, o);
    __syncthreads();
    if (lane == 0) rbuf1[w] = p;
    __syncthreads();
    if (tid == 0) out[g] = rbuf1[0] + rbuf1[1] + rbuf1[2] + rbuf1[3] + b_lin[0];
}

// ---------------- launch ----------------
extern "C" void kernel_launch(void* const* d_in, const int* in_sizes, int n_in,
                              void* d_out, int out_size)
{
    const float* x     = (const float*)d_in[0];
    const int*   ei    = (const int*)  d_in[1];
    const int*   batch = (const int*)  d_in[2];
    const float* W1    = (const float*)d_in[3];
    const float* b1    = (const float*)d_in[4];
    const float* W2    = (const float*)d_in[5];
    const float* b2    = (const float*)d_in[6];
    const float* W_ih  = (const float*)d_in[7];
    /* W_hh = d_in[8] unused: h0 == 0 */
    const float* b_ih  = (const float*)d_in[9];
    const float* b_hh  = (const float*)d_in[10];
    const float* W_lin = (const float*)d_in[11];
    const float* b_lin = (const float*)d_in[12];
    float* out = (float*)d_out;

    const int N = in_sizes[0] / 128;
    const int E = in_sizes[1] / 2;
    const int G = out_size;
    const int* srcp = ei;
    const int* dstp = ei + E;

    float  *p_h;
    __half *p_xwh;
    uint2  *p_wb1, *p_wb2;
    cudaGetSymbolAddress((void**)&p_xwh, g_xwh);
    cudaGetSymbolAddress((void**)&p_h,   g_h);
    cudaGetSymbolAddress((void**)&p_wb1, g_wbuf1);
    cudaGetSymbolAddress((void**)&p_wb2, g_wbuf2);

    static cudaStream_t s_side = nullptr;
    static cudaEvent_t ev_fork = nullptr, ev_join = nullptr;
    if (!s_side) {
        cudaFuncSetAttribute(gemm_tc_kernel,
                             cudaFuncAttributeMaxDynamicSharedMemorySize, SM_GEMM_TOTAL);
        cudaStreamCreateWithFlags(&s_side, cudaStreamNonBlocking);
        cudaEventCreateWithFlags(&ev_fork, cudaEventDisableTiming);
        cudaEventCreateWithFlags(&ev_join, cudaEventDisableTiming);
    }

    const int T = 256;
    int bN   = (N + T - 1) / T;
    int bE   = (E + T - 1) / T;
    int nb   = (N + 255) / 256;
    long long wthreads = (long long)N * 32;
    int bAgg = (int)((wthreads + T - 1) / T);
    int bGemm = (N + 63) / 64;

    // fork: CSR build on side stream, GEMM path on main stream
    cudaEventRecord(ev_fork, 0);
    cudaStreamWaitEvent(s_side, ev_fork, 0);

    // submission slots: wsplit(1), degcnt(2), scan1(3), gemm1(4) <- ncu
    wsplit_kernel<<<(2 * 4096 + T - 1) / T, T>>>(W1, W2);              // main
    degcnt_kernel<<<bE, T, 0, s_side>>>(dstp, batch, E, N);            // side
    scan1_kernel<<<nb, 256, 0, s_side>>>(N);                           // side
    gemm_tc_kernel<<<bGemm, 256, SM_GEMM_TOTAL>>>(x, p_wb1, p_xwh, N); // main <- ncu slot 4
    scan2_kernel<<<1, 512, 0, s_side>>>(nb);                           // side
    scan3_kernel<<<bN, T, 0, s_side>>>(N);                             // side
    scatter_kernel<<<bE, T, 0, s_side>>>(srcp, dstp, E);               // side
    cudaEventRecord(ev_join, s_side);

    cudaStreamWaitEvent(0, ev_join, 0);

    // conv1 aggregate, conv2, pool (serial topology)
    agg_kernel<false><<<bAgg, T>>>(p_xwh, b1, p_h, batch, N);
    gemm_tc_kernel<<<bGemm, 256, SM_GEMM_TOTAL>>>(p_h, p_wb2, p_xwh, N);
    agg_kernel<true><<<bAgg, T>>>(p_xwh, b2, nullptr, batch, N);

    // GRU + LN + head (self-cleans g_sums/g_cnt)
    gru_ln_out_kernel<<<G, 128>>>(W_ih, b_ih, b_hh, W_lin, b_lin, out);
}

// round 16
// speedup vs baseline: 1.2189x; 1.0441x over previous
#include <cuda_runtime.h>
#include <cuda_bf16.h>
#include <cuda_fp16.h>
#include <math.h>
#include <stdint.h>

#define NODES_MAX 100000
#define EDGES_MAX 1600000
#define GRAPHS_MAX 2048

// ---------------- scratch (no allocations allowed) ----------------
__device__ __half g_xwh [NODES_MAX * 128];   // x @ W as fp16 rows (gather + self)
__device__ float  g_h   [NODES_MAX * 128];   // hidden after conv1 (fp32, GEMM2 input)
__device__ float  g_dinv[NODES_MAX];         // rsqrt(deg+1)
__device__ float  g_sums[GRAPHS_MAX * 128];  // pooled sums (self-cleaned by gru)
__device__ float  g_cnt [GRAPHS_MAX];        // nodes per graph (self-cleaned by gru)
__device__ uint2  g_wbuf1[4096];             // W1 fp16 fragment order
__device__ uint2  g_wbuf2[4096];             // W2 likewise
// CSR build
__device__ int    g_deg   [NODES_MAX];       // self-cleaned by scan3
__device__ int    g_scan  [NODES_MAX];
__device__ int    g_bsum  [1024];
__device__ int    g_boff  [1024];
__device__ int    g_rowptr[NODES_MAX + 1];
__device__ int    g_cursor[NODES_MAX];
__device__ int2   g_epack [EDGES_MAX];       // {src, bits(dinv[src]*dinv[dst])} sorted by dst

// ---------------- helpers ----------------
__device__ __forceinline__ void red_add_v4(float* addr, float4 v) {
    asm volatile("red.global.add.v4.f32 [%0], {%1,%2,%3,%4};"
                 :: "l"(addr), "f"(v.x), "f"(v.y), "f"(v.z), "f"(v.w) : "memory");
}
__device__ __forceinline__ void mma_f16(float* c, const uint32_t* a, const uint32_t* b) {
    asm volatile(
        "mma.sync.aligned.m16n8k16.row.col.f32.f16.f16.f32 "
        "{%0,%1,%2,%3},{%4,%5,%6,%7},{%8,%9},{%0,%1,%2,%3};"
        : "+f"(c[0]), "+f"(c[1]), "+f"(c[2]), "+f"(c[3])
        : "r"(a[0]), "r"(a[1]), "r"(a[2]), "r"(a[3]), "r"(b[0]), "r"(b[1]));
}
__device__ __forceinline__ uint32_t smem_u32(const void* p) {
    uint32_t a;
    asm("{ .reg .u64 t; cvta.to.shared.u64 t, %1; cvt.u32.u64 %0, t; }" : "=r"(a) : "l"(p));
    return a;
}
__device__ __forceinline__ void cp_async16(uint32_t dst, const void* src, bool pred) {
    int sz = pred ? 16 : 0;
    asm volatile("cp.async.cg.shared.global [%0], [%1], 16, %2;"
                 :: "r"(dst), "l"(src), "r"(sz) : "memory");
}
__device__ __forceinline__ void cp_commit() {
    asm volatile("cp.async.commit_group;" ::: "memory");
}
template <int NW>
__device__ __forceinline__ void cp_wait_group() {
    asm volatile("cp.async.wait_group %0;" :: "n"(NW) : "memory");
}
__device__ __forceinline__ uint32_t f16pack(float v0, float v1) {
    __half2 t = __floats2half2_rn(v0, v1);
    return *(uint32_t*)&t;
}

// ---------------- degcnt ----------------
__global__ void degcnt_kernel(const int* __restrict__ dst, const int* __restrict__ batch,
                              int E, int N) {
    int i = blockIdx.x * blockDim.x + threadIdx.x;
    if (i < E) atomicAdd(&g_deg[dst[i]], 1);
    unsigned active = __ballot_sync(0xffffffffu, i < N);
    if (i < N) {
        int b = batch[i];
        unsigned m = __match_any_sync(active, b);
        int leader = __ffs(m) - 1;
        if ((threadIdx.x & 31) == leader)
            atomicAdd(&g_cnt[b], (float)__popc(m));
    }
}

// W -> fp16 mma fragment order (single term).
__global__ void wsplit_kernel(const float* __restrict__ W1, const float* __restrict__ W2) {
    int i = blockIdx.x * blockDim.x + threadIdx.x;
    if (i >= 2 * 4096) return;
    int conv = i >> 12;
    int idx = i & 4095;
    int lane = idx & 31, nt = (idx >> 5) & 15, kk = idx >> 9;   // kk 0..7
    int g = lane >> 2, tg = lane & 3;
    int n = nt * 8 + g;
    int k0 = kk * 16 + 2 * tg;
    const float* W = conv ? W2 : W1;
    float v00 = W[(size_t)k0 * 128 + n];
    float v01 = W[(size_t)(k0 + 1) * 128 + n];
    float v10 = W[(size_t)(k0 + 8) * 128 + n];
    float v11 = W[(size_t)(k0 + 9) * 128 + n];
    uint2 o = make_uint2(f16pack(v00, v01), f16pack(v10, v11));
    if (conv) g_wbuf2[idx] = o; else g_wbuf1[idx] = o;
}

// ---------------- scan (3-kernel, proven) ----------------
__global__ void scan1_kernel(int N) {
    int i = blockIdx.x * 256 + threadIdx.x;
    int v = (i < N) ? g_deg[i] : 0;
    int lane = threadIdx.x & 31, w = threadIdx.x >> 5;
    int s = v;
    #pragma unroll
    for (int o = 1; o < 32; o <<= 1) {
        int t = __shfl_up_sync(0xffffffffu, s, o);
        if (lane >= o) s += t;
    }
    __shared__ int wsum[8];
    if (lane == 31) wsum[w] = s;
    __syncthreads();
    if (w == 0) {
        int ss = (lane < 8) ? wsum[lane] : 0;
        #pragma unroll
        for (int o = 1; o < 8; o <<= 1) {
            int u = __shfl_up_sync(0xffffffffu, ss, o);
            if (lane >= o) ss += u;
        }
        if (lane < 8) wsum[lane] = ss;
    }
    __syncthreads();
    s += (w > 0) ? wsum[w - 1] : 0;
    if (i < N) g_scan[i] = s;
    if (threadIdx.x == 255) g_bsum[blockIdx.x] = s;
}

__global__ void scan2_kernel(int nb) {
    int t = threadIdx.x;                     // 512 threads
    int v = (t < nb) ? g_bsum[t] : 0;
    int lane = t & 31, w = t >> 5;
    int s = v;
    #pragma unroll
    for (int o = 1; o < 32; o <<= 1) {
        int u = __shfl_up_sync(0xffffffffu, s, o);
        if (lane >= o) s += u;
    }
    __shared__ int wsum[16];
    if (lane == 31) wsum[w] = s;
    __syncthreads();
    if (w == 0) {
        int ss = (lane < 16) ? wsum[lane] : 0;
        #pragma unroll
        for (int o = 1; o < 16; o <<= 1) {
            int u = __shfl_up_sync(0xffffffffu, ss, o);
            if (lane >= o) ss += u;
        }
        if (lane < 16) wsum[lane] = ss;
    }
    __syncthreads();
    s += (w > 0) ? wsum[w - 1] : 0;
    if (t < nb) g_boff[t] = s;
}

__global__ void scan3_kernel(int N) {
    int i = blockIdx.x * blockDim.x + threadIdx.x;
    if (i >= N) return;
    int b = i >> 8;
    int dv = g_deg[i];
    int incl = ((b > 0) ? g_boff[b - 1] : 0) + g_scan[i];
    g_rowptr[i + 1] = incl;
    g_cursor[i] = incl - dv;
    g_dinv[i] = rsqrtf((float)dv + 1.0f);
    g_deg[i] = 0;                            // self-clean for next call
    if (i == 0) g_rowptr[0] = 0;
}

__global__ void scatter_kernel(const int* __restrict__ src, const int* __restrict__ dst, int E) {
    int e = blockIdx.x * blockDim.x + threadIdx.x;
    if (e >= E) return;
    int d = dst[e];
    int s = src[e];
    int pos = atomicAdd(&g_cursor[d], 1);
    g_epack[pos] = make_int2(s, __float_as_int(g_dinv[s] * g_dinv[d]));
}

// ---------------- tensor GEMM: Ch[M,128] = fp16(A[M,128] @ W), fp16 + ldmatrix ----------
// smem: Ws 32KB + fp16 A-tile 64x136 halfs (17.0KB) = 50.2KB -> 3 CTAs/SM.
static constexpr int SM_WS_BYTES = 4096 * 8;           // 32768
static constexpr int AH_STRIDE   = 136;                // halfs; row step 272B -> ldmatrix conflict-free
static constexpr int SM_GEMM_TOTAL = SM_WS_BYTES + 64 * AH_STRIDE * 2;  // 50176

__global__ __launch_bounds__(256, 3) void gemm_tc_kernel(
    const float* __restrict__ A, const uint2* __restrict__ Wbuf,
    __half* __restrict__ Ch, int M)
{
    extern __shared__ char smem[];
    uint2*  Ws = (uint2*)smem;
    __half* Ah = (__half*)(smem + SM_WS_BYTES);
    uint32_t ws_b = smem_u32(Ws), ah_b = smem_u32(Ah);

    int tid = threadIdx.x, wid = tid >> 5, lane = tid & 31;
    int g = lane >> 2, tg = lane & 3;
    int wm = wid & 1, wn = wid >> 1;         // warp tile: m32 x n32
    int row0 = blockIdx.x * 64;

    // W via cp.async (overlaps the A fill)
    #pragma unroll
    for (int it = 0; it < 8; it++) {
        int idx = it * 256 + tid;
        cp_async16(ws_b + idx * 16, (const char*)Wbuf + idx * 16, true);
    }
    cp_commit();

    // A fill: fp32 LDG -> fp16 STS (2048 float4 total, 8 per thread)
    #pragma unroll
    for (int it = 0; it < 8; it++) {
        int j = it * 256 + tid;              // 0..2047
        int r = j >> 5, c4 = j & 31;         // 32 float4 per row
        bool pred = (row0 + r) < M;
        float4 v = make_float4(0.f, 0.f, 0.f, 0.f);
        if (pred) v = *(const float4*)&A[(size_t)(row0 + r) * 128 + c4 * 4];
        uint2 h;
        h.x = f16pack(v.x, v.y);
        h.y = f16pack(v.z, v.w);
        *(uint2*)&Ah[r * AH_STRIDE + c4 * 4] = h;
    }
    cp_wait_group<0>();
    __syncthreads();

    float acc[2][4][4];
    #pragma unroll
    for (int mi = 0; mi < 2; mi++)
        #pragma unroll
        for (int ni = 0; ni < 4; ni++)
            #pragma unroll
            for (int j = 0; j < 4; j++) acc[mi][ni][j] = 0.f;

    // per-lane ldmatrix row/col: lanes 0-7 rows 0-7 @k0, 8-15 rows 8-15 @k0,
    // 16-23 rows 0-7 @k8, 24-31 rows 8-15 @k8
    int frag_row = lane & 15;
    int col8 = (lane >> 4) * 8;

    #pragma unroll
    for (int kstep = 0; kstep < 8; kstep++) {
        uint32_t a[2][4];
        #pragma unroll
        for (int mi = 0; mi < 2; mi++) {
            uint32_t addr = ah_b +
                ((wm * 32 + mi * 16 + frag_row) * AH_STRIDE + kstep * 16 + col8) * 2;
            asm volatile("ldmatrix.sync.aligned.m8n8.x4.shared.b16 {%0,%1,%2,%3}, [%4];"
                : "=r"(a[mi][0]), "=r"(a[mi][1]), "=r"(a[mi][2]), "=r"(a[mi][3])
                : "r"(addr));
        }
        #pragma unroll
        for (int ni = 0; ni < 4; ni++) {
            int nt = wn * 4 + ni;
            uint2 w2 = Ws[kstep * 512 + nt * 32 + lane];
            uint32_t bh[2] = { w2.x, w2.y };
            #pragma unroll
            for (int mi = 0; mi < 2; mi++)
                mma_f16(acc[mi][ni], a[mi], bh);
        }
    }

    #pragma unroll
    for (int mi = 0; mi < 2; mi++) {
        int r0 = row0 + wm * 32 + mi * 16 + g;
        int r1 = r0 + 8;
        #pragma unroll
        for (int ni = 0; ni < 4; ni++) {
            int col = wn * 32 + ni * 8 + tg * 2;
            if (r0 < M)
                *(__half2*)&Ch[(size_t)r0 * 128 + col] = __floats2half2_rn(acc[mi][ni][0], acc[mi][ni][1]);
            if (r1 < M)
                *(__half2*)&Ch[(size_t)r1 * 128 + col] = __floats2half2_rn(acc[mi][ni][2], acc[mi][ni][3]);
        }
    }
}

// ---------------- CSR aggregation (split-warp + epack software prefetch) ------------------
template <bool POOL>
__global__ void agg_kernel(const __half* __restrict__ xwh, const float* __restrict__ bias,
                           float* __restrict__ hout, const int* __restrict__ batch, int N)
{
    int d = (blockIdx.x * blockDim.x + threadIdx.x) >> 5;
    int lane = threadIdx.x & 31;
    if (d >= N) return;
    int hf = lane >> 4, hl = lane & 15;        // half-warp id, lane within half

    float di = g_dinv[d];
    float sl = di * di;

    float acc[8];
    {   // self term (half 0 only; half 1 starts at zero)
        uint4 us = *(const uint4*)&xwh[(size_t)d * 128 + hl * 8];
        float2 a = __half22float2(*(__half2*)&us.x);
        float2 b = __half22float2(*(__half2*)&us.y);
        float2 c = __half22float2(*(__half2*)&us.z);
        float2 e = __half22float2(*(__half2*)&us.w);
        float m = hf ? 0.f : sl;
        acc[0] = a.x * m; acc[1] = a.y * m; acc[2] = b.x * m; acc[3] = b.y * m;
        acc[4] = c.x * m; acc[5] = c.y * m; acc[6] = e.x * m; acc[7] = e.y * m;
    }

    int e0 = g_rowptr[d], e1 = g_rowptr[d + 1];
    int e = e0 + hf;                            // halves interleave edges
    int2 pA = (e < e1)     ? g_epack[e]     : make_int2(0, 0);
    int2 pB = (e + 2 < e1) ? g_epack[e + 2] : make_int2(0, 0);

    for (; e + 2 < e1; e += 4) {
        int en = e + 4;
        int2 qA = (en < e1)     ? g_epack[en]     : make_int2(0, 0);
        int2 qB = (en + 2 < e1) ? g_epack[en + 2] : make_int2(0, 0);

        float n0 = __int_as_float(pA.y);
        float n1 = __int_as_float(pB.y);
        uint4 u0 = *(const uint4*)&xwh[(size_t)pA.x * 128 + hl * 8];
        uint4 u1 = *(const uint4*)&xwh[(size_t)pB.x * 128 + hl * 8];
        float2 t;
        t = __half22float2(*(__half2*)&u0.x); acc[0] = fmaf(t.x, n0, acc[0]); acc[1] = fmaf(t.y, n0, acc[1]);
        t = __half22float2(*(__half2*)&u0.y); acc[2] = fmaf(t.x, n0, acc[2]); acc[3] = fmaf(t.y, n0, acc[3]);
        t = __half22float2(*(__half2*)&u0.z); acc[4] = fmaf(t.x, n0, acc[4]); acc[5] = fmaf(t.y, n0, acc[5]);
        t = __half22float2(*(__half2*)&u0.w); acc[6] = fmaf(t.x, n0, acc[6]); acc[7] = fmaf(t.y, n0, acc[7]);
        t = __half22float2(*(__half2*)&u1.x); acc[0] = fmaf(t.x, n1, acc[0]); acc[1] = fmaf(t.y, n1, acc[1]);
        t = __half22float2(*(__half2*)&u1.y); acc[2] = fmaf(t.x, n1, acc[2]); acc[3] = fmaf(t.y, n1, acc[3]);
        t = __half22float2(*(__half2*)&u1.z); acc[4] = fmaf(t.x, n1, acc[4]); acc[5] = fmaf(t.y, n1, acc[5]);
        t = __half22float2(*(__half2*)&u1.w); acc[6] = fmaf(t.x, n1, acc[6]); acc[7] = fmaf(t.y, n1, acc[7]);

        pA = qA; pB = qB;
    }
    if (e < e1) {
        float nm = __int_as_float(pA.y);
        uint4 u = *(const uint4*)&xwh[(size_t)pA.x * 128 + hl * 8];
        float2 t;
        t = __half22float2(*(__half2*)&u.x); acc[0] = fmaf(t.x, nm, acc[0]); acc[1] = fmaf(t.y, nm, acc[1]);
        t = __half22float2(*(__half2*)&u.y); acc[2] = fmaf(t.x, nm, acc[2]); acc[3] = fmaf(t.y, nm, acc[3]);
        t = __half22float2(*(__half2*)&u.z); acc[4] = fmaf(t.x, nm, acc[4]); acc[5] = fmaf(t.y, nm, acc[5]);
        t = __half22float2(*(__half2*)&u.w); acc[6] = fmaf(t.x, nm, acc[6]); acc[7] = fmaf(t.y, nm, acc[7]);
    }

    #pragma unroll
    for (int j = 0; j < 8; j++)
        acc[j] += __shfl_down_sync(0xffffffffu, acc[j], 16);

    if (hf == 0) {
        float4 b0 = *(const float4*)&bias[hl * 8];
        float4 b1 = *(const float4*)&bias[hl * 8 + 4];
        float4 o0 = make_float4(acc[0] + b0.x, acc[1] + b0.y, acc[2] + b0.z, acc[3] + b0.w);
        float4 o1 = make_float4(acc[4] + b1.x, acc[5] + b1.y, acc[6] + b1.z, acc[7] + b1.w);
        if (POOL) {
            int gi = batch[d];
            red_add_v4(&g_sums[(size_t)gi * 128 + hl * 8], o0);
            red_add_v4(&g_sums[(size_t)gi * 128 + hl * 8 + 4], o1);
        } else {
            o0.x = fmaxf(o0.x, 0.f); o0.y = fmaxf(o0.y, 0.f);
            o0.z = fmaxf(o0.z, 0.f); o0.w = fmaxf(o0.w, 0.f);
            o1.x = fmaxf(o1.x, 0.f); o1.y = fmaxf(o1.y, 0.f);
            o1.z = fmaxf(o1.z, 0.f); o1.w = fmaxf(o1.w, 0.f);
            *(float4*)&hout[(size_t)d * 128 + hl * 8]     = o0;
            *(float4*)&hout[(size_t)d * 128 + hl * 8 + 4] = o1;
        }
    }
}

// ---------------- GRU step (h0=0) + relu + layernorm + linear head; self-cleans sums/cnt --
__global__ __launch_bounds__(128) void gru_ln_out_kernel(
    const float* __restrict__ W_ih, const float* __restrict__ b_ih,
    const float* __restrict__ b_hh, const float* __restrict__ W_lin,
    const float* __restrict__ b_lin, float* __restrict__ out)
{
    int g = blockIdx.x;
    int tid = threadIdx.x;
    int lane = tid & 31, w = tid >> 5;

    __shared__ float gs[128];
    __shared__ float gi[384];
    __shared__ float rbuf1[4], rbuf2[4];

    float cnt = fmaxf(g_cnt[g], 1.0f);
    gs[tid] = g_sums[(size_t)g * 128 + tid] / cnt;
    g_sums[(size_t)g * 128 + tid] = 0.f;     // self-clean for next call
    if (tid == 0) g_cnt[g] = 0.f;
    __syncthreads();

    for (int j = w; j < 384; j += 4) {
        const float* wr = W_ih + (size_t)j * 128;
        float s = 0.f;
        #pragma unroll
        for (int t = 0; t < 4; t++) {
            int k = lane + t * 32;
            s += gs[k] * wr[k];
        }
        #pragma unroll
        for (int o = 16; o > 0; o >>= 1) s += __shfl_xor_sync(0xffffffffu, s, o);
        if (lane == 0) gi[j] = s + b_ih[j];
    }
    __syncthreads();

    float r  = 1.f / (1.f + expf(-(gi[tid]       + b_hh[tid])));
    float z  = 1.f / (1.f + expf(-(gi[tid + 128] + b_hh[tid + 128])));
    float nn = tanhf(gi[tid + 256] + r * b_hh[tid + 256]);
    float v  = fmaxf((1.f - z) * nn, 0.f);

    float s1 = v, s2 = v * v;
    #pragma unroll
    for (int o = 16; o > 0; o >>= 1) {
        s1 += __shfl_xor_sync(0xffffffffu, s1, o);
        s2 += __shfl_xor_sync(0xffffffffu, s2, o);
    }
    if (lane == 0) { rbuf1[w] = s1; rbuf2[w] = s2; }
    __syncthreads();
    float S1 = rbuf1[0] + rbuf1[1] + rbuf1[2] + rbuf1[3];
    float S2 = rbuf2[0] + rbuf2[1] + rbuf2[2] + rbuf2[3];
    float mu  = S1 * (1.f / 128.f);
    float var = S2 * (1.f / 128.f) - mu * mu;
    float y = (v - mu) * rsqrtf(var + 1e-5f);

    float p = y * W_lin[tid];
    #pragma unroll
    for (int o = 16; o > 0; o >>= 1) p += __shfl_xor_sync(0xffffffffu, p, o);
    __syncthreads();
    if (lane == 0) rbuf1[w] = p;
    __syncthreads();
    if (tid == 0) out[g] = rbuf1[0] + rbuf1[1] + rbuf1[2] + rbuf1[3] + b_lin[0];
}

// ---------------- launch ----------------
extern "C" void kernel_launch(void* const* d_in, const int* in_sizes, int n_in,
                              void* d_out, int out_size)
{
    const float* x     = (const float*)d_in[0];
    const int*   ei    = (const int*)  d_in[1];
    const int*   batch = (const int*)  d_in[2];
    const float* W1    = (const float*)d_in[3];
    const float* b1    = (const float*)d_in[4];
    const float* W2    = (const float*)d_in[5];
    const float* b2    = (const float*)d_in[6];
    const float* W_ih  = (const float*)d_in[7];
    /* W_hh = d_in[8] unused: h0 == 0 */
    const float* b_ih  = (const float*)d_in[9];
    const float* b_hh  = (const float*)d_in[10];
    const float* W_lin = (const float*)d_in[11];
    const float* b_lin = (const float*)d_in[12];
    float* out = (float*)d_out;

    const int N = in_sizes[0] / 128;
    const int E = in_sizes[1] / 2;
    const int G = out_size;
    const int* srcp = ei;
    const int* dstp = ei + E;

    float  *p_h;
    __half *p_xwh;
    uint2  *p_wb1, *p_wb2;
    cudaGetSymbolAddress((void**)&p_xwh, g_xwh);
    cudaGetSymbolAddress((void**)&p_h,   g_h);
    cudaGetSymbolAddress((void**)&p_wb1, g_wbuf1);
    cudaGetSymbolAddress((void**)&p_wb2, g_wbuf2);

    static cudaStream_t s_side = nullptr;
    static cudaEvent_t ev_fork = nullptr, ev_join = nullptr;
    if (!s_side) {
        cudaFuncSetAttribute(gemm_tc_kernel,
                             cudaFuncAttributeMaxDynamicSharedMemorySize, SM_GEMM_TOTAL);
        cudaStreamCreateWithFlags(&s_side, cudaStreamNonBlocking);
        cudaEventCreateWithFlags(&ev_fork, cudaEventDisableTiming);
        cudaEventCreateWithFlags(&ev_join, cudaEventDisableTiming);
    }

    const int T = 256;
    int bN   = (N + T - 1) / T;
    int bE   = (E + T - 1) / T;
    int nb   = (N + 255) / 256;
    long long wthreads = (long long)N * 32;
    int bAgg = (int)((wthreads + T - 1) / T);
    int bGemm = (N + 63) / 64;

    // fork: CSR build on side stream, GEMM path on main stream
    cudaEventRecord(ev_fork, 0);
    cudaStreamWaitEvent(s_side, ev_fork, 0);

    // submission slots: wsplit(1), degcnt(2), scan1(3), gemm1(4) <- ncu
    wsplit_kernel<<<(2 * 4096 + T - 1) / T, T>>>(W1, W2);              // main
    degcnt_kernel<<<bE, T, 0, s_side>>>(dstp, batch, E, N);            // side
    scan1_kernel<<<nb, 256, 0, s_side>>>(N);                           // side
    gemm_tc_kernel<<<bGemm, 256, SM_GEMM_TOTAL>>>(x, p_wb1, p_xwh, N); // main <- ncu slot 4
    scan2_kernel<<<1, 512, 0, s_side>>>(nb);                           // side
    scan3_kernel<<<bN, T, 0, s_side>>>(N);                             // side
    scatter_kernel<<<bE, T, 0, s_side>>>(srcp, dstp, E);               // side
    cudaEventRecord(ev_join, s_side);

    cudaStreamWaitEvent(0, ev_join, 0);

    // conv1 aggregate, conv2, pool (serial topology)
    agg_kernel<false><<<bAgg, T>>>(p_xwh, b1, p_h, batch, N);
    gemm_tc_kernel<<<bGemm, 256, SM_GEMM_TOTAL>>>(p_h, p_wb2, p_xwh, N);
    agg_kernel<true><<<bAgg, T>>>(p_xwh, b2, nullptr, batch, N);

    // GRU + LN + head (self-cleans g_sums/g_cnt)
    gru_ln_out_kernel<<<G, 128>>>(W_ih, b_ih, b_hh, W_lin, b_lin, out);
}

// round 17
// speedup vs baseline: 1.2256x; 1.0055x over previous
#include <cuda_runtime.h>
#include <cuda_bf16.h>
#include <cuda_fp16.h>
#include <math.h>
#include <stdint.h>

#define NODES_MAX 100000
#define EDGES_MAX 1600000
#define GRAPHS_MAX 2048

// ---------------- scratch (no allocations allowed) ----------------
__device__ __half g_xh  [NODES_MAX * 128];   // fp16 copy of x (GEMM1 input)
__device__ __half g_xwh [NODES_MAX * 128];   // fp16(x @ W) rows (gather + self)
__device__ __half g_hh  [NODES_MAX * 128];   // fp16 hidden after conv1 (GEMM2 input)
__device__ float  g_dinv[NODES_MAX];         // rsqrt(deg+1)
__device__ float  g_sums[GRAPHS_MAX * 128];  // pooled sums (self-cleaned by gru)
__device__ float  g_cnt [GRAPHS_MAX];        // nodes per graph (self-cleaned by gru)
__device__ uint2  g_wbuf1[4096];             // W1 fp16 fragment order
__device__ uint2  g_wbuf2[4096];             // W2 likewise
// CSR build
__device__ int    g_deg   [NODES_MAX];       // self-cleaned by scan3
__device__ int    g_scan  [NODES_MAX];
__device__ int    g_bsum  [1024];
__device__ int    g_boff  [1024];
__device__ int    g_rowptr[NODES_MAX + 1];
__device__ int    g_cursor[NODES_MAX];
__device__ int2   g_epack [EDGES_MAX];       // {src, bits(dinv[src]*dinv[dst])} sorted by dst

// ---------------- helpers ----------------
__device__ __forceinline__ void red_add_v4(float* addr, float4 v) {
    asm volatile("red.global.add.v4.f32 [%0], {%1,%2,%3,%4};"
                 :: "l"(addr), "f"(v.x), "f"(v.y), "f"(v.z), "f"(v.w) : "memory");
}
__device__ __forceinline__ void mma_f16(float* c, const uint32_t* a, const uint32_t* b) {
    asm volatile(
        "mma.sync.aligned.m16n8k16.row.col.f32.f16.f16.f32 "
        "{%0,%1,%2,%3},{%4,%5,%6,%7},{%8,%9},{%0,%1,%2,%3};"
        : "+f"(c[0]), "+f"(c[1]), "+f"(c[2]), "+f"(c[3])
        : "r"(a[0]), "r"(a[1]), "r"(a[2]), "r"(a[3]), "r"(b[0]), "r"(b[1]));
}
__device__ __forceinline__ uint32_t smem_u32(const void* p) {
    uint32_t a;
    asm("{ .reg .u64 t; cvta.to.shared.u64 t, %1; cvt.u32.u64 %0, t; }" : "=r"(a) : "l"(p));
    return a;
}
__device__ __forceinline__ void cp_async16(uint32_t dst, const void* src, bool pred) {
    int sz = pred ? 16 : 0;
    asm volatile("cp.async.cg.shared.global [%0], [%1], 16, %2;"
                 :: "r"(dst), "l"(src), "r"(sz) : "memory");
}
__device__ __forceinline__ void cp_commit() {
    asm volatile("cp.async.commit_group;" ::: "memory");
}
template <int NW>
__device__ __forceinline__ void cp_wait_group() {
    asm volatile("cp.async.wait_group %0;" :: "n"(NW) : "memory");
}
__device__ __forceinline__ uint32_t f16pack(float v0, float v1) {
    __half2 t = __floats2half2_rn(v0, v1);
    return *(uint32_t*)&t;
}

// ---------------- degcnt ----------------
__global__ void degcnt_kernel(const int* __restrict__ dst, const int* __restrict__ batch,
                              int E, int N) {
    int i = blockIdx.x * blockDim.x + threadIdx.x;
    if (i < E) atomicAdd(&g_deg[dst[i]], 1);
    unsigned active = __ballot_sync(0xffffffffu, i < N);
    if (i < N) {
        int b = batch[i];
        unsigned m = __match_any_sync(active, b);
        int leader = __ffs(m) - 1;
        if ((threadIdx.x & 31) == leader)
            atomicAdd(&g_cnt[b], (float)__popc(m));
    }
}

// W -> fp16 mma fragment order (single term).
__global__ void wsplit_kernel(const float* __restrict__ W1, const float* __restrict__ W2) {
    int i = blockIdx.x * blockDim.x + threadIdx.x;
    if (i >= 2 * 4096) return;
    int conv = i >> 12;
    int idx = i & 4095;
    int lane = idx & 31, nt = (idx >> 5) & 15, kk = idx >> 9;   // kk 0..7
    int g = lane >> 2, tg = lane & 3;
    int n = nt * 8 + g;
    int k0 = kk * 16 + 2 * tg;
    const float* W = conv ? W2 : W1;
    float v00 = W[(size_t)k0 * 128 + n];
    float v01 = W[(size_t)(k0 + 1) * 128 + n];
    float v10 = W[(size_t)(k0 + 8) * 128 + n];
    float v11 = W[(size_t)(k0 + 9) * 128 + n];
    uint2 o = make_uint2(f16pack(v00, v01), f16pack(v10, v11));
    if (conv) g_wbuf2[idx] = o; else g_wbuf1[idx] = o;
}

// x -> fp16 copy (numerically identical to the old in-GEMM conversion)
__global__ void xcvt_kernel(const float* __restrict__ x, __half* __restrict__ xh, int n4) {
    int i = blockIdx.x * blockDim.x + threadIdx.x;
    if (i >= n4) return;
    float4 v = *(const float4*)&x[(size_t)i * 4];
    uint2 h = make_uint2(f16pack(v.x, v.y), f16pack(v.z, v.w));
    *(uint2*)&xh[(size_t)i * 4] = h;
}

// ---------------- scan (3-kernel, proven) ----------------
__global__ void scan1_kernel(int N) {
    int i = blockIdx.x * 256 + threadIdx.x;
    int v = (i < N) ? g_deg[i] : 0;
    int lane = threadIdx.x & 31, w = threadIdx.x >> 5;
    int s = v;
    #pragma unroll
    for (int o = 1; o < 32; o <<= 1) {
        int t = __shfl_up_sync(0xffffffffu, s, o);
        if (lane >= o) s += t;
    }
    __shared__ int wsum[8];
    if (lane == 31) wsum[w] = s;
    __syncthreads();
    if (w == 0) {
        int ss = (lane < 8) ? wsum[lane] : 0;
        #pragma unroll
        for (int o = 1; o < 8; o <<= 1) {
            int u = __shfl_up_sync(0xffffffffu, ss, o);
            if (lane >= o) ss += u;
        }
        if (lane < 8) wsum[lane] = ss;
    }
    __syncthreads();
    s += (w > 0) ? wsum[w - 1] : 0;
    if (i < N) g_scan[i] = s;
    if (threadIdx.x == 255) g_bsum[blockIdx.x] = s;
}

__global__ void scan2_kernel(int nb) {
    int t = threadIdx.x;                     // 512 threads
    int v = (t < nb) ? g_bsum[t] : 0;
    int lane = t & 31, w = t >> 5;
    int s = v;
    #pragma unroll
    for (int o = 1; o < 32; o <<= 1) {
        int u = __shfl_up_sync(0xffffffffu, s, o);
        if (lane >= o) s += u;
    }
    __shared__ int wsum[16];
    if (lane == 31) wsum[w] = s;
    __syncthreads();
    if (w == 0) {
        int ss = (lane < 16) ? wsum[lane] : 0;
        #pragma unroll
        for (int o = 1; o < 16; o <<= 1) {
            int u = __shfl_up_sync(0xffffffffu, ss, o);
            if (lane >= o) ss += u;
        }
        if (lane < 16) wsum[lane] = ss;
    }
    __syncthreads();
    s += (w > 0) ? wsum[w - 1] : 0;
    if (t < nb) g_boff[t] = s;
}

__global__ void scan3_kernel(int N) {
    int i = blockIdx.x * blockDim.x + threadIdx.x;
    if (i >= N) return;
    int b = i >> 8;
    int dv = g_deg[i];
    int incl = ((b > 0) ? g_boff[b - 1] : 0) + g_scan[i];
    g_rowptr[i + 1] = incl;
    g_cursor[i] = incl - dv;
    g_dinv[i] = rsqrtf((float)dv + 1.0f);
    g_deg[i] = 0;                            // self-clean for next call
    if (i == 0) g_rowptr[0] = 0;
}

__global__ void scatter_kernel(const int* __restrict__ src, const int* __restrict__ dst, int E) {
    int e = blockIdx.x * blockDim.x + threadIdx.x;
    if (e >= E) return;
    int d = dst[e];
    int s = src[e];
    int pos = atomicAdd(&g_cursor[d], 1);
    g_epack[pos] = make_int2(s, __float_as_int(g_dinv[s] * g_dinv[d]));
}

// ---------------- tensor GEMM: Ch[M,128] = fp16(A[M,128] @ W), fp16 A via cp.async -------
// smem: Ws 32KB + fp16 A-tile 64x136 halfs (17.0KB) = 50.2KB -> 3 CTAs/SM.
static constexpr int SM_WS_BYTES = 4096 * 8;           // 32768
static constexpr int AH_STRIDE   = 136;                // halfs; row step 272B (16B-aligned)
static constexpr int SM_GEMM_TOTAL = SM_WS_BYTES + 64 * AH_STRIDE * 2;  // 50176

__global__ __launch_bounds__(256, 3) void gemm_tc_kernel(
    const __half* __restrict__ A, const uint2* __restrict__ Wbuf,
    __half* __restrict__ Ch, int M)
{
    extern __shared__ char smem[];
    uint2*  Ws = (uint2*)smem;
    __half* Ah = (__half*)(smem + SM_WS_BYTES);
    uint32_t ws_b = smem_u32(Ws), ah_b = smem_u32(Ah);

    int tid = threadIdx.x, wid = tid >> 5, lane = tid & 31;
    int g = lane >> 2, tg = lane & 3;
    int wm = wid & 1, wn = wid >> 1;         // warp tile: m32 x n32
    int row0 = blockIdx.x * 64;

    // W tile (2048 x 16B, 8/thread) + A tile (1024 x 16B, 4/thread), all async
    #pragma unroll
    for (int it = 0; it < 8; it++) {
        int idx = it * 256 + tid;
        cp_async16(ws_b + idx * 16, (const char*)Wbuf + idx * 16, true);
    }
    #pragma unroll
    for (int it = 0; it < 4; it++) {
        int j = it * 256 + tid;              // 0..1023
        int r = j >> 4, c = j & 15;          // 16 chunks of 16B per row
        bool pred = (row0 + r) < M;
        int r_eff = pred ? (row0 + r) : 0;
        cp_async16(ah_b + (r * AH_STRIDE + c * 8) * 2,
                   A + (size_t)r_eff * 128 + c * 8, pred);
    }
    cp_commit();
    cp_wait_group<0>();
    __syncthreads();

    float acc[2][4][4];
    #pragma unroll
    for (int mi = 0; mi < 2; mi++)
        #pragma unroll
        for (int ni = 0; ni < 4; ni++)
            #pragma unroll
            for (int j = 0; j < 4; j++) acc[mi][ni][j] = 0.f;

    int frag_row = lane & 15;
    int col8 = (lane >> 4) * 8;

    #pragma unroll
    for (int kstep = 0; kstep < 8; kstep++) {
        uint32_t a[2][4];
        #pragma unroll
        for (int mi = 0; mi < 2; mi++) {
            uint32_t addr = ah_b +
                ((wm * 32 + mi * 16 + frag_row) * AH_STRIDE + kstep * 16 + col8) * 2;
            asm volatile("ldmatrix.sync.aligned.m8n8.x4.shared.b16 {%0,%1,%2,%3}, [%4];"
                : "=r"(a[mi][0]), "=r"(a[mi][1]), "=r"(a[mi][2]), "=r"(a[mi][3])
                : "r"(addr));
        }
        #pragma unroll
        for (int ni = 0; ni < 4; ni++) {
            int nt = wn * 4 + ni;
            uint2 w2 = Ws[kstep * 512 + nt * 32 + lane];
            uint32_t bh[2] = { w2.x, w2.y };
            #pragma unroll
            for (int mi = 0; mi < 2; mi++)
                mma_f16(acc[mi][ni], a[mi], bh);
        }
    }

    #pragma unroll
    for (int mi = 0; mi < 2; mi++) {
        int r0 = row0 + wm * 32 + mi * 16 + g;
        int r1 = r0 + 8;
        #pragma unroll
        for (int ni = 0; ni < 4; ni++) {
            int col = wn * 32 + ni * 8 + tg * 2;
            if (r0 < M)
                *(__half2*)&Ch[(size_t)r0 * 128 + col] = __floats2half2_rn(acc[mi][ni][0], acc[mi][ni][1]);
            if (r1 < M)
                *(__half2*)&Ch[(size_t)r1 * 128 + col] = __floats2half2_rn(acc[mi][ni][2], acc[mi][ni][3]);
        }
    }
}

// ---------------- CSR aggregation (split-warp + epack software prefetch) ------------------
// POOL=false: writes fp16 h rows (bit-identical to gemm2's old in-kernel conversion).
template <bool POOL>
__global__ void agg_kernel(const __half* __restrict__ xwh, const float* __restrict__ bias,
                           __half* __restrict__ hout, const int* __restrict__ batch, int N)
{
    int d = (blockIdx.x * blockDim.x + threadIdx.x) >> 5;
    int lane = threadIdx.x & 31;
    if (d >= N) return;
    int hf = lane >> 4, hl = lane & 15;        // half-warp id, lane within half

    float di = g_dinv[d];
    float sl = di * di;

    float acc[8];
    {   // self term (half 0 only; half 1 starts at zero)
        uint4 us = *(const uint4*)&xwh[(size_t)d * 128 + hl * 8];
        float2 a = __half22float2(*(__half2*)&us.x);
        float2 b = __half22float2(*(__half2*)&us.y);
        float2 c = __half22float2(*(__half2*)&us.z);
        float2 e = __half22float2(*(__half2*)&us.w);
        float m = hf ? 0.f : sl;
        acc[0] = a.x * m; acc[1] = a.y * m; acc[2] = b.x * m; acc[3] = b.y * m;
        acc[4] = c.x * m; acc[5] = c.y * m; acc[6] = e.x * m; acc[7] = e.y * m;
    }

    int e0 = g_rowptr[d], e1 = g_rowptr[d + 1];
    int e = e0 + hf;                            // halves interleave edges
    int2 pA = (e < e1)     ? g_epack[e]     : make_int2(0, 0);
    int2 pB = (e + 2 < e1) ? g_epack[e + 2] : make_int2(0, 0);

    for (; e + 2 < e1; e += 4) {
        int en = e + 4;
        int2 qA = (en < e1)     ? g_epack[en]     : make_int2(0, 0);
        int2 qB = (en + 2 < e1) ? g_epack[en + 2] : make_int2(0, 0);

        float n0 = __int_as_float(pA.y);
        float n1 = __int_as_float(pB.y);
        uint4 u0 = *(const uint4*)&xwh[(size_t)pA.x * 128 + hl * 8];
        uint4 u1 = *(const uint4*)&xwh[(size_t)pB.x * 128 + hl * 8];
        float2 t;
        t = __half22float2(*(__half2*)&u0.x); acc[0] = fmaf(t.x, n0, acc[0]); acc[1] = fmaf(t.y, n0, acc[1]);
        t = __half22float2(*(__half2*)&u0.y); acc[2] = fmaf(t.x, n0, acc[2]); acc[3] = fmaf(t.y, n0, acc[3]);
        t = __half22float2(*(__half2*)&u0.z); acc[4] = fmaf(t.x, n0, acc[4]); acc[5] = fmaf(t.y, n0, acc[5]);
        t = __half22float2(*(__half2*)&u0.w); acc[6] = fmaf(t.x, n0, acc[6]); acc[7] = fmaf(t.y, n0, acc[7]);
        t = __half22float2(*(__half2*)&u1.x); acc[0] = fmaf(t.x, n1, acc[0]); acc[1] = fmaf(t.y, n1, acc[1]);
        t = __half22float2(*(__half2*)&u1.y); acc[2] = fmaf(t.x, n1, acc[2]); acc[3] = fmaf(t.y, n1, acc[3]);
        t = __half22float2(*(__half2*)&u1.z); acc[4] = fmaf(t.x, n1, acc[4]); acc[5] = fmaf(t.y, n1, acc[5]);
        t = __half22float2(*(__half2*)&u1.w); acc[6] = fmaf(t.x, n1, acc[6]); acc[7] = fmaf(t.y, n1, acc[7]);

        pA = qA; pB = qB;
    }
    if (e < e1) {
        float nm = __int_as_float(pA.y);
        uint4 u = *(const uint4*)&xwh[(size_t)pA.x * 128 + hl * 8];
        float2 t;
        t = __half22float2(*(__half2*)&u.x); acc[0] = fmaf(t.x, nm, acc[0]); acc[1] = fmaf(t.y, nm, acc[1]);
        t = __half22float2(*(__half2*)&u.y); acc[2] = fmaf(t.x, nm, acc[2]); acc[3] = fmaf(t.y, nm, acc[3]);
        t = __half22float2(*(__half2*)&u.z); acc[4] = fmaf(t.x, nm, acc[4]); acc[5] = fmaf(t.y, nm, acc[5]);
        t = __half22float2(*(__half2*)&u.w); acc[6] = fmaf(t.x, nm, acc[6]); acc[7] = fmaf(t.y, nm, acc[7]);
    }

    #pragma unroll
    for (int j = 0; j < 8; j++)
        acc[j] += __shfl_down_sync(0xffffffffu, acc[j], 16);

    if (hf == 0) {
        float4 b0 = *(const float4*)&bias[hl * 8];
        float4 b1 = *(const float4*)&bias[hl * 8 + 4];
        float4 o0 = make_float4(acc[0] + b0.x, acc[1] + b0.y, acc[2] + b0.z, acc[3] + b0.w);
        float4 o1 = make_float4(acc[4] + b1.x, acc[5] + b1.y, acc[6] + b1.z, acc[7] + b1.w);
        if (POOL) {
            int gi = batch[d];
            red_add_v4(&g_sums[(size_t)gi * 128 + hl * 8], o0);
            red_add_v4(&g_sums[(size_t)gi * 128 + hl * 8 + 4], o1);
        } else {
            o0.x = fmaxf(o0.x, 0.f); o0.y = fmaxf(o0.y, 0.f);
            o0.z = fmaxf(o0.z, 0.f); o0.w = fmaxf(o0.w, 0.f);
            o1.x = fmaxf(o1.x, 0.f); o1.y = fmaxf(o1.y, 0.f);
            o1.z = fmaxf(o1.z, 0.f); o1.w = fmaxf(o1.w, 0.f);
            uint4 h;
            h.x = f16pack(o0.x, o0.y);
            h.y = f16pack(o0.z, o0.w);
            h.z = f16pack(o1.x, o1.y);
            h.w = f16pack(o1.z, o1.w);
            *(uint4*)&hout[(size_t)d * 128 + hl * 8] = h;
        }
    }
}

// ---------------- GRU step (h0=0) + relu + layernorm + linear head; self-cleans sums/cnt --
__global__ __launch_bounds__(128) void gru_ln_out_kernel(
    const float* __restrict__ W_ih, const float* __restrict__ b_ih,
    const float* __restrict__ b_hh, const float* __restrict__ W_lin,
    const float* __restrict__ b_lin, float* __restrict__ out)
{
    int g = blockIdx.x;
    int tid = threadIdx.x;
    int lane = tid & 31, w = tid >> 5;

    __shared__ float gs[128];
    __shared__ float gi[384];
    __shared__ float rbuf1[4], rbuf2[4];

    float cnt = fmaxf(g_cnt[g], 1.0f);
    gs[tid] = g_sums[(size_t)g * 128 + tid] / cnt;
    g_sums[(size_t)g * 128 + tid] = 0.f;     // self-clean for next call
    if (tid == 0) g_cnt[g] = 0.f;
    __syncthreads();

    for (int j = w; j < 384; j += 4) {
        const float* wr = W_ih + (size_t)j * 128;
        float s = 0.f;
        #pragma unroll
        for (int t = 0; t < 4; t++) {
            int k = lane + t * 32;
            s += gs[k] * wr[k];
        }
        #pragma unroll
        for (int o = 16; o > 0; o >>= 1) s += __shfl_xor_sync(0xffffffffu, s, o);
        if (lane == 0) gi[j] = s + b_ih[j];
    }
    __syncthreads();

    float r  = 1.f / (1.f + expf(-(gi[tid]       + b_hh[tid])));
    float z  = 1.f / (1.f + expf(-(gi[tid + 128] + b_hh[tid + 128])));
    float nn = tanhf(gi[tid + 256] + r * b_hh[tid + 256]);
    float v  = fmaxf((1.f - z) * nn, 0.f);

    float s1 = v, s2 = v * v;
    #pragma unroll
    for (int o = 16; o > 0; o >>= 1) {
        s1 += __shfl_xor_sync(0xffffffffu, s1, o);
        s2 += __shfl_xor_sync(0xffffffffu, s2, o);
    }
    if (lane == 0) { rbuf1[w] = s1; rbuf2[w] = s2; }
    __syncthreads();
    float S1 = rbuf1[0] + rbuf1[1] + rbuf1[2] + rbuf1[3];
    float S2 = rbuf2[0] + rbuf2[1] + rbuf2[2] + rbuf2[3];
    float mu  = S1 * (1.f / 128.f);
    float var = S2 * (1.f / 128.f) - mu * mu;
    float y = (v - mu) * rsqrtf(var + 1e-5f);

    float p = y * W_lin[tid];
    #pragma unroll
    for (int o = 16; o > 0; o >>= 1) p += __shfl_xor_sync(0xffffffffu, p, o);
    __syncthreads();
    if (lane == 0) rbuf1[w] = p;
    __syncthreads();
    if (tid == 0) out[g] = rbuf1[0] + rbuf1[1] + rbuf1[2] + rbuf1[3] + b_lin[0];
}

// ---------------- launch ----------------
extern "C" void kernel_launch(void* const* d_in, const int* in_sizes, int n_in,
                              void* d_out, int out_size)
{
    const float* x     = (const float*)d_in[0];
    const int*   ei    = (const int*)  d_in[1];
    const int*   batch = (const int*)  d_in[2];
    const float* W1    = (const float*)d_in[3];
    const float* b1    = (const float*)d_in[4];
    const float* W2    = (const float*)d_in[5];
    const float* b2    = (const float*)d_in[6];
    const float* W_ih  = (const float*)d_in[7];
    /* W_hh = d_in[8] unused: h0 == 0 */
    const float* b_ih  = (const float*)d_in[9];
    const float* b_hh  = (const float*)d_in[10];
    const float* W_lin = (const float*)d_in[11];
    const float* b_lin = (const float*)d_in[12];
    float* out = (float*)d_out;

    const int N = in_sizes[0] / 128;
    const int E = in_sizes[1] / 2;
    const int G = out_size;
    const int* srcp = ei;
    const int* dstp = ei + E;

    __half *p_xh, *p_xwh, *p_hh;
    uint2  *p_wb1, *p_wb2;
    cudaGetSymbolAddress((void**)&p_xh,  g_xh);
    cudaGetSymbolAddress((void**)&p_xwh, g_xwh);
    cudaGetSymbolAddress((void**)&p_hh,  g_hh);
    cudaGetSymbolAddress((void**)&p_wb1, g_wbuf1);
    cudaGetSymbolAddress((void**)&p_wb2, g_wbuf2);

    static cudaStream_t s_side = nullptr;
    static cudaEvent_t ev_fork = nullptr, ev_join = nullptr;
    if (!s_side) {
        cudaFuncSetAttribute(gemm_tc_kernel,
                             cudaFuncAttributeMaxDynamicSharedMemorySize, SM_GEMM_TOTAL);
        cudaStreamCreateWithFlags(&s_side, cudaStreamNonBlocking);
        cudaEventCreateWithFlags(&ev_fork, cudaEventDisableTiming);
        cudaEventCreateWithFlags(&ev_join, cudaEventDisableTiming);
    }

    const int T = 256;
    int bN   = (N + T - 1) / T;
    int bE   = (E + T - 1) / T;
    int nb   = (N + 255) / 256;
    int n4   = N * 32;
    int bX   = (n4 + T - 1) / T;
    long long wthreads = (long long)N * 32;
    int bAgg = (int)((wthreads + T - 1) / T);
    int bGemm = (N + 63) / 64;

    // fork: CSR build on side stream, GEMM path on main stream
    cudaEventRecord(ev_fork, 0);
    cudaStreamWaitEvent(s_side, ev_fork, 0);

    // submission slots: wsplit(1), degcnt(2), xcvt(3), gemm1(4) <- ncu
    wsplit_kernel<<<(2 * 4096 + T - 1) / T, T>>>(W1, W2);                 // main
    degcnt_kernel<<<bE, T, 0, s_side>>>(dstp, batch, E, N);               // side
    xcvt_kernel<<<bX, T>>>(x, p_xh, n4);                                  // main
    gemm_tc_kernel<<<bGemm, 256, SM_GEMM_TOTAL>>>(p_xh, p_wb1, p_xwh, N); // main <- ncu slot 4
    scan1_kernel<<<nb, 256, 0, s_side>>>(N);                              // side
    scan2_kernel<<<1, 512, 0, s_side>>>(nb);                              // side
    scan3_kernel<<<bN, T, 0, s_side>>>(N);                                // side
    scatter_kernel<<<bE, T, 0, s_side>>>(srcp, dstp, E);                  // side
    cudaEventRecord(ev_join, s_side);

    cudaStreamWaitEvent(0, ev_join, 0);

    // conv1 aggregate (fp16 h), conv2, pool (serial topology)
    agg_kernel<false><<<bAgg, T>>>(p_xwh, b1, p_hh, batch, N);
    gemm_tc_kernel<<<bGemm, 256, SM_GEMM_TOTAL>>>(p_hh, p_wb2, p_xwh, N);
    agg_kernel<true><<<bAgg, T>>>(p_xwh, b2, nullptr, batch, N);

    // GRU + LN + head (self-cleans g_sums/g_cnt)
    gru_ln_out_kernel<<<G, 128>>>(W_ih, b_ih, b_hh, W_lin, b_lin, out);
}